// round 9
// baseline (speedup 1.0000x reference)
#include <cuda_runtime.h>
#include <cuda_bf16.h>
#include <cstdint>

// ---------------- problem constants ----------------
#define BZn   16
#define TTn   962
#define CCn   384
#define DIn   768
#define DSTn  16
#define DTRn  24
#define XPn   56          // DTR + 2*DSTATE
#define MMn   (BZn*TTn)   // 15392
#define IMG_BLK 1966080   // 80*384*64

// ---------------- scratch (device globals; no allocation allowed) ----------------
__device__ __align__(16) float g_X   [MMn*CCn];
__device__ __align__(16) float g_XLN [MMn*CCn];
__device__ __align__(16) float g_XFC1[MMn*CCn];
__device__ __align__(16) float g_XFLIP[MMn*CCn];
__device__ __align__(16) float g_XZ  [(size_t)MMn*2*DIn];
__device__ __align__(16) float g_XCONV[(size_t)MMn*DIn];
__device__ __align__(16) float g_XDBL[(size_t)MMn*XPn];
__device__ __align__(16) float g_DT  [(size_t)MMn*DIn];
__device__ __align__(16) float g_Y   [(size_t)MMn*DIn];
__device__ __align__(16) float g_FM  [MMn*CCn];
__device__ __align__(16) float g_BM  [MMn*CCn];
__device__ __align__(16) float g_RELU[MMn*CCn];

// ---------------- MUFU-free math helpers ----------------
__device__ __forceinline__ float fexp2(float y){
    y = fminf(fmaxf(y, -126.f), 126.f);
    float n = rintf(y);
    float f = y - n;
    float g = f * 0.69314718055994531f;
    float p = 1.98412698e-4f;
    p = fmaf(p, g, 1.38888889e-3f);
    p = fmaf(p, g, 8.33333333e-3f);
    p = fmaf(p, g, 4.16666667e-2f);
    p = fmaf(p, g, 1.66666667e-1f);
    p = fmaf(p, g, 0.5f);
    p = fmaf(p, g, 1.0f);
    p = fmaf(p, g, 1.0f);
    return p * __int_as_float(((int)n + 127) << 23);
}
__device__ __forceinline__ float fexp(float x){ return fexp2(x * 1.4426950408889634f); }
__device__ __forceinline__ float frcp_fast(float w){
    float r = __int_as_float(0x7EF311C3 - __float_as_int(w));
    r = r * fmaf(-w, r, 2.0f);
    r = r * fmaf(-w, r, 2.0f);
    r = r * fmaf(-w, r, 2.0f);
    return r;
}
__device__ __forceinline__ float silu_f(float x){ return x * frcp_fast(1.0f + fexp(-x)); }
__device__ __forceinline__ float softplus_f(float x){
    float ax = fabsf(x);
    float e  = fexp(-ax);
    float t  = e * frcp_fast(2.0f + e);
    float t2 = t * t;
    float p  = 2.0f/9.0f;
    p = fmaf(p, t2, 2.0f/7.0f);
    p = fmaf(p, t2, 2.0f/5.0f);
    p = fmaf(p, t2, 2.0f/3.0f);
    p = fmaf(p, t2, 2.0f);
    return fmaxf(x, 0.0f) + p * t;
}

// ---------------- mma / ldmatrix helpers (non-'a' features, sm_80+) ----------------
__device__ __forceinline__ uint32_t sptr(const void* p){
    return (uint32_t)__cvta_generic_to_shared(p);
}
__device__ __forceinline__ void ldm_x4(uint32_t r[4], uint32_t addr){
    asm volatile("ldmatrix.sync.aligned.m8n8.x4.shared.b16 {%0,%1,%2,%3}, [%4];"
        : "=r"(r[0]), "=r"(r[1]), "=r"(r[2]), "=r"(r[3]) : "r"(addr));
}
__device__ __forceinline__ void mma_bf16(float* d, const uint32_t* a, const uint32_t* b){
    asm volatile("mma.sync.aligned.m16n8k16.row.col.f32.bf16.bf16.f32 "
        "{%0,%1,%2,%3}, {%4,%5,%6,%7}, {%8,%9}, {%0,%1,%2,%3};"
        : "+f"(d[0]), "+f"(d[1]), "+f"(d[2]), "+f"(d[3])
        : "r"(a[0]), "r"(a[1]), "r"(a[2]), "r"(a[3]), "r"(b[0]), "r"(b[1]));
}
__device__ __forceinline__ uint32_t pk2(float x, float y){
    __nv_bfloat162 t(__float2bfloat16(x), __float2bfloat16(y));
    return *reinterpret_cast<uint32_t*>(&t);
}
// split 8 fp32 -> hi plane (8 bf16) + lo plane (8 bf16)
__device__ __forceinline__ void split8(const float4& a, const float4& b, uint4& hi, uint4& lo){
    float h0 = __bfloat162float(__float2bfloat16(a.x));
    float h1 = __bfloat162float(__float2bfloat16(a.y));
    float h2 = __bfloat162float(__float2bfloat16(a.z));
    float h3 = __bfloat162float(__float2bfloat16(a.w));
    float h4 = __bfloat162float(__float2bfloat16(b.x));
    float h5 = __bfloat162float(__float2bfloat16(b.y));
    float h6 = __bfloat162float(__float2bfloat16(b.z));
    float h7 = __bfloat162float(__float2bfloat16(b.w));
    hi.x = pk2(a.x, a.y); hi.y = pk2(a.z, a.w);
    hi.z = pk2(b.x, b.y); hi.w = pk2(b.z, b.w);
    lo.x = pk2(a.x - h0, a.y - h1); lo.y = pk2(a.z - h2, a.w - h3);
    lo.z = pk2(b.x - h4, b.y - h5); lo.w = pk2(b.z - h6, b.w - h7);
}

// ---------------- pipelined HMMA GEMM with fused bf16x3 split ----------------
// Co[m,n] = sum_k A[m,k]*W[n,k] (+bias/act).  A fp32 [M x lda], W fp32 [N x ldw].
// Kloop: multiple of 32 (loop bound). Klim: true K (cols >= Klim treated as 0).
// Block tile 128x128, K-chunk 32, 256 threads, warp tile 32x64.
// EPI: 0=none 1=bias 2=bias+leaky(0.2) 3=bias+softplus
#define PLANEn (128*40)
template<int EPI>
__global__ void __launch_bounds__(256)
mma_gemm2(const float* __restrict__ A, int lda,
          const float* __restrict__ W, int ldw,
          const float* __restrict__ bias, float* __restrict__ Co,
          int M, int N, int Kloop, int Klim)
{
    extern __shared__ __align__(16) __nv_bfloat16 sm[];  // 2 bufs x 4 planes x 128 x 40

    const int tid = threadIdx.x;
    const int lid = tid & 31, wid = tid >> 5;
    const int warp_m = wid & 3, warp_n = wid >> 2;
    const int m0 = blockIdx.x * 128, n0 = blockIdx.y * 128;
    const int lr = tid >> 2, lc = tid & 3;

    float acc[2][8][4];
#pragma unroll
    for (int i=0;i<2;i++)
#pragma unroll
        for (int j=0;j<8;j++)
#pragma unroll
            for (int q=0;q<4;q++) acc[i][j][q] = 0.f;

    float4 ra[4], rb[4];

    auto LD = [&](int kb){
#pragma unroll
        for (int p=0;p<2;p++){
            int row = lr + p*64;
#pragma unroll
            for (int h=0;h<2;h++){
                int c = kb + lc*8 + h*4;
                float4 va = make_float4(0,0,0,0), vb = make_float4(0,0,0,0);
                if (c + 3 < Klim){
                    if (m0 + row < M) va = *(const float4*)(A + (size_t)(m0+row)*lda + c);
                    if (n0 + row < N) vb = *(const float4*)(W + (size_t)(n0+row)*ldw + c);
                }
                ra[p*2+h] = va; rb[p*2+h] = vb;
            }
        }
    };
    auto STS = [&](int buf){
        __nv_bfloat16* base = sm + buf*4*PLANEn;
#pragma unroll
        for (int p=0;p<2;p++){
            int row = lr + p*64;
            int bo = row*40 + lc*8;
            uint4 hi, lo;
            split8(ra[p*2], ra[p*2+1], hi, lo);
            *(uint4*)(base + bo) = hi;
            *(uint4*)(base + PLANEn + bo) = lo;
            split8(rb[p*2], rb[p*2+1], hi, lo);
            *(uint4*)(base + 2*PLANEn + bo) = hi;
            *(uint4*)(base + 3*PLANEn + bo) = lo;
        }
    };
    auto COMP = [&](int buf){
        __nv_bfloat16* Ah = sm + buf*4*PLANEn;
        __nv_bfloat16* Al = Ah + PLANEn;
        __nv_bfloat16* Bh = Ah + 2*PLANEn;
        __nv_bfloat16* Bl = Ah + 3*PLANEn;
#pragma unroll
        for (int kk=0; kk<2; kk++){
            uint32_t ah[2][4], al[2][4];
#pragma unroll
            for (int i=0;i<2;i++){
                int arow = warp_m*32 + i*16 + (lid & 15);
                int acol = kk*16 + (lid >> 4)*8;
                ldm_x4(ah[i], sptr(Ah + arow*40 + acol));
                ldm_x4(al[i], sptr(Al + arow*40 + acol));
            }
#pragma unroll
            for (int jp=0; jp<4; jp++){
                uint32_t bh[4], bl[4];
                int brow = warp_n*64 + jp*16 + ((lid >> 4) << 3) + (lid & 7);
                int bcol = kk*16 + ((lid >> 3) & 1)*8;
                ldm_x4(bh, sptr(Bh + brow*40 + bcol));
                ldm_x4(bl, sptr(Bl + brow*40 + bcol));
#pragma unroll
                for (int i=0;i<2;i++){
                    mma_bf16(acc[i][jp*2],   ah[i], &bh[0]);
                    mma_bf16(acc[i][jp*2],   al[i], &bh[0]);
                    mma_bf16(acc[i][jp*2],   ah[i], &bl[0]);
                    mma_bf16(acc[i][jp*2+1], ah[i], &bh[2]);
                    mma_bf16(acc[i][jp*2+1], al[i], &bh[2]);
                    mma_bf16(acc[i][jp*2+1], ah[i], &bl[2]);
                }
            }
        }
    };

    LD(0); STS(0); __syncthreads();
    const int nkc = Kloop >> 5;
    for (int kc = 0; kc < nkc; kc++){
        bool more = (kc + 1) < nkc;
        if (more) LD((kc+1) << 5);        // gmem loads overlap compute below
        COMP(kc & 1);
        if (more){
            STS((kc+1) & 1);
            __syncthreads();
        }
    }

    // epilogue: d0,d1 -> (row t/4, col 2*(t%4)); d2,d3 -> row+8
#pragma unroll
    for (int i=0;i<2;i++){
#pragma unroll
        for (int j=0;j<8;j++){
            int r = m0 + warp_m*32 + i*16 + (lid >> 2);
            int c = n0 + warp_n*64 + j*8 + (lid & 3)*2;
            if (c < N){
                float b0 = 0.f, b1 = 0.f;
                if (EPI >= 1){ b0 = bias[c]; b1 = bias[c+1]; }
                float v0 = acc[i][j][0] + b0, v1 = acc[i][j][1] + b1;
                float v2 = acc[i][j][2] + b0, v3 = acc[i][j][3] + b1;
                if (EPI == 2){
                    v0 = (v0 >= 0.f) ? v0 : 0.2f*v0;
                    v1 = (v1 >= 0.f) ? v1 : 0.2f*v1;
                    v2 = (v2 >= 0.f) ? v2 : 0.2f*v2;
                    v3 = (v3 >= 0.f) ? v3 : 0.2f*v3;
                }
                if (EPI == 3){
                    v0 = softplus_f(v0); v1 = softplus_f(v1);
                    v2 = softplus_f(v2); v3 = softplus_f(v3);
                }
                if (r < M)     *(float2*)(Co + (size_t)r*N + c)     = make_float2(v0, v1);
                if (r + 8 < M) *(float2*)(Co + (size_t)(r+8)*N + c) = make_float2(v2, v3);
            }
        }
    }
}
#define SMEM_G2 (2*4*PLANEn*2)   // 81920 bytes

// ---------------- token assembly ----------------
__global__ void assemble_kernel(const float* __restrict__ img,
                                const float* __restrict__ lid,
                                const float* __restrict__ rad,
                                const float* __restrict__ gps,
                                const float* __restrict__ pos)
{
    int c = threadIdx.x;
    int t = blockIdx.x;
    int b = blockIdx.y;
    float v;
    if (t < 960){
        int q = t >> 6, p = t & 63;
        int grp = q / 5, s = q - grp*5;
        int band = c >> 7;
        int code = grp + band; if (code >= 3) code -= 3;
        const float* sel = (code == 0) ? img : (code == 1) ? lid : rad;
        v = sel[((size_t)((b*5 + s)*384 + c) << 6) + p];
    } else {
        v = gps[((size_t)(b*2 + (t-960)))*384 + c];
    }
    g_X[((size_t)(b*TTn + t))*CCn + c] = v + pos[t*CCn + c];
}

// ---------------- LayerNorm ----------------
__global__ void ln_kernel(const float* __restrict__ x, const float* __restrict__ gam,
                          const float* __restrict__ bet, float* __restrict__ out)
{
    int m = blockIdx.x, tid = threadIdx.x;
    const float* row = x + (size_t)m*CCn;
    float v0 = row[tid], v1 = row[tid+128], v2 = row[tid+256];
    float s = v0+v1+v2;
    float q = v0*v0 + v1*v1 + v2*v2;
#pragma unroll
    for (int off=16; off; off>>=1){
        s += __shfl_xor_sync(0xffffffffu, s, off);
        q += __shfl_xor_sync(0xffffffffu, q, off);
    }
    __shared__ float ss[4], sq[4];
    if ((tid & 31) == 0){ ss[tid>>5] = s; sq[tid>>5] = q; }
    __syncthreads();
    s = ss[0]+ss[1]+ss[2]+ss[3];
    q = sq[0]+sq[1]+sq[2]+sq[3];
    float mean = s * (1.0f/384.0f);
    float var  = q * (1.0f/384.0f) - mean*mean;
    float rstd = rsqrtf(var + 1e-5f);
    float* orow = out + (size_t)m*CCn;
    orow[tid]     = (v0-mean)*rstd*gam[tid]     + bet[tid];
    orow[tid+128] = (v1-mean)*rstd*gam[tid+128] + bet[tid+128];
    orow[tid+256] = (v2-mean)*rstd*gam[tid+256] + bet[tid+256];
}

// ---------------- time-flip ----------------
__global__ void flip_kernel(){
    int idx = blockIdx.x*blockDim.x + threadIdx.x;
    if (idx >= MMn*96) return;
    int row = idx / 96, c4 = idx - row*96;
    int b = row / TTn, t = row - b*TTn;
    ((float4*)g_XFLIP)[idx] =
        ((const float4*)g_XFC1)[(size_t)(b*TTn + (TTn-1-t))*96 + c4];
}

// ---------------- depthwise causal conv + SiLU ----------------
__global__ void conv_silu_kernel(const float* __restrict__ cw, const float* __restrict__ cb){
    int idx = blockIdx.x*blockDim.x + threadIdx.x;
    if (idx >= MMn*DIn) return;
    int d = idx % DIn;
    int m = idx / DIn;
    int b = m / TTn;
    int t = m - b*TTn;
    const float* base = g_XZ + (size_t)(b*TTn) * (2*DIn) + d;
    float acc = cb[d];
    float w0 = cw[d*4+0], w1 = cw[d*4+1], w2 = cw[d*4+2], w3 = cw[d*4+3];
    if (t >= 3) acc = fmaf(w0, base[(size_t)(t-3)*(2*DIn)], acc);
    if (t >= 2) acc = fmaf(w1, base[(size_t)(t-2)*(2*DIn)], acc);
    if (t >= 1) acc = fmaf(w2, base[(size_t)(t-1)*(2*DIn)], acc);
    acc = fmaf(w3, base[(size_t)t*(2*DIn)], acc);
    g_XCONV[idx] = silu_f(acc);
}

// ---------------- selective scan ----------------
__global__ void __launch_bounds__(256)
scan_kernel(const float* __restrict__ a_log, const float* __restrict__ Dp){
    int gtid = blockIdx.x*256 + threadIdx.x;
    int lane = gtid & 3;
    int pidx = gtid >> 2;
    int b = pidx / DIn;
    int d = pidx - b*DIn;

    float cA[4], h[4];
#pragma unroll
    for (int j=0;j<4;j++){
        cA[j] = -fexp(a_log[d*16 + lane + j*4]) * 1.4426950408889634f;
        h[j] = 0.f;
    }
    float Dv = Dp[d];
    int mbase = b * TTn;
    for (int t = 0; t < TTn; t++){
        int m = mbase + t;
        float dtv = g_DT   [(size_t)m*DIn + d];
        float xv  = g_XCONV[(size_t)m*DIn + d];
        float dtx = dtv * xv;
        const float* bc = g_XDBL + (size_t)m*XPn;
        float y = 0.f;
#pragma unroll
        for (int j=0;j<4;j++){
            float Bv = bc[24 + lane + j*4];
            float Cv = bc[40 + lane + j*4];
            float a  = fexp2(dtv * cA[j]);
            h[j] = fmaf(h[j], a, dtx * Bv);
            y    = fmaf(h[j], Cv, y);
        }
        y += __shfl_xor_sync(0xffffffffu, y, 1);
        y += __shfl_xor_sync(0xffffffffu, y, 2);
        if (lane == 0){
            float zv = g_XZ[(size_t)m*(2*DIn) + DIn + d];
            g_Y[(size_t)m*DIn + d] = (y + Dv*xv) * silu_f(zv);
        }
    }
}

// ---------------- combine ----------------
__global__ void combine_kernel(){
    int idx = blockIdx.x*blockDim.x + threadIdx.x;
    if (idx >= MMn*96) return;
    float4 bm = ((const float4*)g_BM)[idx];
    float4 fm = ((const float4*)g_FM)[idx];
    float4 rl = ((const float4*)g_RELU)[idx];
    float4 o;
    o.x = bm.x*(rl.x+fm.x);
    o.y = bm.y*(rl.y+fm.y);
    o.z = bm.z*(rl.z+fm.z);
    o.w = bm.w*(rl.w+fm.w);
    ((float4*)g_X)[idx] = o;
}

// ---------------- final LN + scatter ----------------
__global__ void final_kernel(const float* __restrict__ gam, const float* __restrict__ bet,
                             float* __restrict__ out)
{
    int m = blockIdx.x, tid = threadIdx.x;
    int b = m / TTn, t = m - b*TTn;
    const float* row = g_X + (size_t)m*CCn;
    float v0 = row[tid], v1 = row[tid+128], v2 = row[tid+256];
    float s = v0+v1+v2;
    float q = v0*v0 + v1*v1 + v2*v2;
#pragma unroll
    for (int off=16; off; off>>=1){
        s += __shfl_xor_sync(0xffffffffu, s, off);
        q += __shfl_xor_sync(0xffffffffu, q, off);
    }
    __shared__ float ss[4], sq[4];
    if ((tid & 31) == 0){ ss[tid>>5] = s; sq[tid>>5] = q; }
    __syncthreads();
    s = ss[0]+ss[1]+ss[2]+ss[3];
    q = sq[0]+sq[1]+sq[2]+sq[3];
    float mean = s * (1.0f/384.0f);
    float var  = q * (1.0f/384.0f) - mean*mean;
    float rstd = rsqrtf(var + 1e-5f);
    float vs[3] = {v0, v1, v2};
#pragma unroll
    for (int i=0;i<3;i++){
        int c = tid + i*128;
        float val = (vs[i]-mean)*rstd*gam[c] + bet[c];
        size_t dst;
        if (t < 960){
            int qq = t >> 6, p = t & 63;
            int sec = qq / 5, sidx = qq - sec*5;
            dst = (size_t)sec*IMG_BLK + (((size_t)((b*5+sidx)*384 + c)) << 6) + p;
        } else {
            dst = (size_t)3*IMG_BLK + (size_t)(b*2 + (t-960))*384 + c;
        }
        out[dst] = val;
    }
}

// ---------------- launch ----------------
extern "C" void kernel_launch(void* const* d_in, const int* in_sizes, int n_in,
                              void* d_out, int out_size)
{
    const float* img      = (const float*)d_in[0];
    const float* lid      = (const float*)d_in[1];
    const float* rad      = (const float*)d_in[2];
    const float* gps      = (const float*)d_in[3];
    const float* pos      = (const float*)d_in[4];
    const float* ln1_g    = (const float*)d_in[5];
    const float* ln1_b    = (const float*)d_in[6];
    const float* fc1_w    = (const float*)d_in[7];
    const float* fc1_b    = (const float*)d_in[8];
    const float* fc2_w    = (const float*)d_in[9];
    const float* fc2_b    = (const float*)d_in[10];
    const float* in_proj_w= (const float*)d_in[11];
    const float* conv_w   = (const float*)d_in[12];
    const float* conv_b   = (const float*)d_in[13];
    const float* x_proj_w = (const float*)d_in[14];
    const float* dt_proj_w= (const float*)d_in[15];
    const float* dt_proj_b= (const float*)d_in[16];
    const float* A_log    = (const float*)d_in[17];
    const float* D_param  = (const float*)d_in[18];
    const float* out_proj_w=(const float*)d_in[19];
    const float* ln_f_g   = (const float*)d_in[20];
    const float* ln_f_b   = (const float*)d_in[21];

    float *pX, *pXLN, *pXFC1, *pXFLIP, *pXZ, *pXCONV, *pXDBL, *pDT, *pY, *pFM, *pBM, *pRELU;
    cudaGetSymbolAddress((void**)&pX,    g_X);
    cudaGetSymbolAddress((void**)&pXLN,  g_XLN);
    cudaGetSymbolAddress((void**)&pXFC1, g_XFC1);
    cudaGetSymbolAddress((void**)&pXFLIP,g_XFLIP);
    cudaGetSymbolAddress((void**)&pXZ,   g_XZ);
    cudaGetSymbolAddress((void**)&pXCONV,g_XCONV);
    cudaGetSymbolAddress((void**)&pXDBL, g_XDBL);
    cudaGetSymbolAddress((void**)&pDT,   g_DT);
    cudaGetSymbolAddress((void**)&pY,    g_Y);
    cudaGetSymbolAddress((void**)&pFM,   g_FM);
    cudaGetSymbolAddress((void**)&pBM,   g_BM);
    cudaGetSymbolAddress((void**)&pRELU, g_RELU);

    cudaFuncSetAttribute(mma_gemm2<0>, cudaFuncAttributeMaxDynamicSharedMemorySize, SMEM_G2);
    cudaFuncSetAttribute(mma_gemm2<1>, cudaFuncAttributeMaxDynamicSharedMemorySize, SMEM_G2);
    cudaFuncSetAttribute(mma_gemm2<2>, cudaFuncAttributeMaxDynamicSharedMemorySize, SMEM_G2);
    cudaFuncSetAttribute(mma_gemm2<3>, cudaFuncAttributeMaxDynamicSharedMemorySize, SMEM_G2);

    assemble_kernel<<<dim3(TTn, BZn), 384>>>(img, lid, rad, gps, pos);

    const int gm = (MMn + 127) / 128;              // 121
    const int EW = (MMn*96 + 255)/256;
    const int CW = (MMn*DIn + 255)/256;

    for (int l = 0; l < 4; l++){
        ln_kernel<<<MMn,128>>>(pX, ln1_g + l*CCn, ln1_b + l*CCn, pXLN);
        // fc1 (+bias): [MM,384] x [384,384]
        mma_gemm2<1><<<dim3(gm,3),256,SMEM_G2>>>(pXLN, CCn, fc1_w + (size_t)l*CCn*CCn, CCn,
                                                 fc1_b + l*CCn, pXFC1, MMn, CCn, CCn, CCn);
        flip_kernel<<<EW,256>>>();
        for (int dir = 0; dir < 2; dir++){
            int pd = l*2 + dir;
            const float* Ain = dir ? pXFLIP : pXFC1;
            // in_proj: [MM,384] x [1536,384]
            mma_gemm2<0><<<dim3(gm,12),256,SMEM_G2>>>(Ain, CCn,
                                                      in_proj_w + (size_t)pd*2*DIn*CCn, CCn,
                                                      nullptr, pXZ, MMn, 2*DIn, CCn, CCn);
            conv_silu_kernel<<<CW,256>>>(conv_w + (size_t)pd*DIn*4, conv_b + (size_t)pd*DIn);
            // x_proj: [MM,768] x [56,768]
            mma_gemm2<0><<<dim3(gm,1),256,SMEM_G2>>>(pXCONV, DIn,
                                                     x_proj_w + (size_t)pd*XPn*DIn, DIn,
                                                     nullptr, pXDBL, MMn, XPn, DIn, DIn);
            // dt_proj: [MM,24(of 56)] x [768,24], softplus  (Kloop=32, Klim=24)
            mma_gemm2<3><<<dim3(gm,6),256,SMEM_G2>>>(pXDBL, XPn,
                                                     dt_proj_w + (size_t)pd*DIn*DTRn, DTRn,
                                                     dt_proj_b + (size_t)pd*DIn, pDT,
                                                     MMn, DIn, 32, DTRn);
            scan_kernel<<<192,256>>>(A_log + (size_t)pd*DIn*DSTn, D_param + (size_t)pd*DIn);
            // out_proj: [MM,768] x [384,768]
            mma_gemm2<0><<<dim3(gm,3),256,SMEM_G2>>>(pY, DIn,
                                                     out_proj_w + (size_t)pd*CCn*DIn, DIn,
                                                     nullptr, dir ? pBM : pFM, MMn, CCn, DIn, DIn);
        }
        // fc2 + leaky
        mma_gemm2<2><<<dim3(gm,3),256,SMEM_G2>>>(pXFLIP, CCn, fc2_w + (size_t)l*CCn*CCn, CCn,
                                                 fc2_b + l*CCn, pRELU, MMn, CCn, CCn, CCn);
        combine_kernel<<<EW,256>>>();
    }

    final_kernel<<<MMn,128>>>(ln_f_g, ln_f_b, (float*)d_out);
}

// round 14
// speedup vs baseline: 2.2659x; 2.2659x over previous
#include <cuda_runtime.h>
#include <cuda_bf16.h>
#include <cstdint>

// ---------------- problem constants ----------------
#define BZn   16
#define TTn   962
#define CCn   384
#define DIn   768
#define DSTn  16
#define DTRn  24
#define XPn   56          // DTR + 2*DSTATE
#define MMn   (BZn*TTn)   // 15392
#define IMG_BLK 1966080   // 80*384*64

// ---------------- scratch (device globals; no allocation allowed) ----------------
__device__ __align__(16) float g_X   [MMn*CCn];
__device__ __align__(16) float g_XLN [MMn*CCn];
__device__ __align__(16) float g_XFC1[MMn*CCn];
__device__ __align__(16) float g_XFLIP[MMn*CCn];
__device__ __align__(16) float g_XZ  [(size_t)MMn*2*DIn];
__device__ __align__(16) float g_XCONV[(size_t)MMn*DIn];
__device__ __align__(16) float g_XDBL[(size_t)MMn*XPn];
__device__ __align__(16) float g_DT  [(size_t)MMn*DIn];
__device__ __align__(16) float g_Y   [(size_t)MMn*DIn];
__device__ __align__(16) float g_FM  [MMn*CCn];
__device__ __align__(16) float g_BM  [MMn*CCn];
__device__ __align__(16) float g_RELU[MMn*CCn];

// ---------------- MUFU-free math helpers ----------------
__device__ __forceinline__ float fexp2(float y){
    y = fminf(fmaxf(y, -126.f), 126.f);
    float n = rintf(y);
    float f = y - n;
    float g = f * 0.69314718055994531f;
    float p = 1.98412698e-4f;
    p = fmaf(p, g, 1.38888889e-3f);
    p = fmaf(p, g, 8.33333333e-3f);
    p = fmaf(p, g, 4.16666667e-2f);
    p = fmaf(p, g, 1.66666667e-1f);
    p = fmaf(p, g, 0.5f);
    p = fmaf(p, g, 1.0f);
    p = fmaf(p, g, 1.0f);
    return p * __int_as_float(((int)n + 127) << 23);
}
__device__ __forceinline__ float fexp(float x){ return fexp2(x * 1.4426950408889634f); }
__device__ __forceinline__ float frcp_fast(float w){
    float r = __int_as_float(0x7EF311C3 - __float_as_int(w));
    r = r * fmaf(-w, r, 2.0f);
    r = r * fmaf(-w, r, 2.0f);
    r = r * fmaf(-w, r, 2.0f);
    return r;
}
__device__ __forceinline__ float silu_f(float x){ return x * frcp_fast(1.0f + fexp(-x)); }
__device__ __forceinline__ float softplus_f(float x){
    float ax = fabsf(x);
    float e  = fexp(-ax);
    float t  = e * frcp_fast(2.0f + e);
    float t2 = t * t;
    float p  = 2.0f/9.0f;
    p = fmaf(p, t2, 2.0f/7.0f);
    p = fmaf(p, t2, 2.0f/5.0f);
    p = fmaf(p, t2, 2.0f/3.0f);
    p = fmaf(p, t2, 2.0f);
    return fmaxf(x, 0.0f) + p * t;
}

// ---------------- mma / ldmatrix helpers (non-'a' features, sm_80+) ----------------
__device__ __forceinline__ uint32_t sptr(const void* p){
    return (uint32_t)__cvta_generic_to_shared(p);
}
__device__ __forceinline__ void ldm_x4(uint32_t r[4], uint32_t addr){
    asm volatile("ldmatrix.sync.aligned.m8n8.x4.shared.b16 {%0,%1,%2,%3}, [%4];"
        : "=r"(r[0]), "=r"(r[1]), "=r"(r[2]), "=r"(r[3]) : "r"(addr));
}
__device__ __forceinline__ void mma_bf16(float* d, const uint32_t* a, const uint32_t* b){
    asm volatile("mma.sync.aligned.m16n8k16.row.col.f32.bf16.bf16.f32 "
        "{%0,%1,%2,%3}, {%4,%5,%6,%7}, {%8,%9}, {%0,%1,%2,%3};"
        : "+f"(d[0]), "+f"(d[1]), "+f"(d[2]), "+f"(d[3])
        : "r"(a[0]), "r"(a[1]), "r"(a[2]), "r"(a[3]), "r"(b[0]), "r"(b[1]));
}
__device__ __forceinline__ uint32_t pk2(float x, float y){
    __nv_bfloat162 t(__float2bfloat16(x), __float2bfloat16(y));
    return *reinterpret_cast<uint32_t*>(&t);
}
__device__ __forceinline__ void split8(const float4& a, const float4& b, uint4& hi, uint4& lo){
    float h0 = __bfloat162float(__float2bfloat16(a.x));
    float h1 = __bfloat162float(__float2bfloat16(a.y));
    float h2 = __bfloat162float(__float2bfloat16(a.z));
    float h3 = __bfloat162float(__float2bfloat16(a.w));
    float h4 = __bfloat162float(__float2bfloat16(b.x));
    float h5 = __bfloat162float(__float2bfloat16(b.y));
    float h6 = __bfloat162float(__float2bfloat16(b.z));
    float h7 = __bfloat162float(__float2bfloat16(b.w));
    hi.x = pk2(a.x, a.y); hi.y = pk2(a.z, a.w);
    hi.z = pk2(b.x, b.y); hi.w = pk2(b.z, b.w);
    lo.x = pk2(a.x - h0, a.y - h1); lo.y = pk2(a.z - h2, a.w - h3);
    lo.z = pk2(b.x - h4, b.y - h5); lo.w = pk2(b.z - h6, b.w - h7);
}

// ---------------- pipelined HMMA GEMM with fused bf16x3 split ----------------
#define PLANEn (128*40)
template<int EPI>
__global__ void __launch_bounds__(256)
mma_gemm2(const float* __restrict__ A, int lda,
          const float* __restrict__ W, int ldw,
          const float* __restrict__ bias, float* __restrict__ Co,
          int M, int N, int Kloop, int Klim)
{
    extern __shared__ __align__(16) __nv_bfloat16 sm[];

    const int tid = threadIdx.x;
    const int lid = tid & 31, wid = tid >> 5;
    const int warp_m = wid & 3, warp_n = wid >> 2;
    const int m0 = blockIdx.x * 128, n0 = blockIdx.y * 128;
    const int lr = tid >> 2, lc = tid & 3;

    float acc[2][8][4];
#pragma unroll
    for (int i=0;i<2;i++)
#pragma unroll
        for (int j=0;j<8;j++)
#pragma unroll
            for (int q=0;q<4;q++) acc[i][j][q] = 0.f;

    float4 ra[4], rb[4];

    auto LD = [&](int kb){
#pragma unroll
        for (int p=0;p<2;p++){
            int row = lr + p*64;
#pragma unroll
            for (int h=0;h<2;h++){
                int c = kb + lc*8 + h*4;
                float4 va = make_float4(0,0,0,0), vb = make_float4(0,0,0,0);
                if (c + 3 < Klim){
                    if (m0 + row < M) va = *(const float4*)(A + (size_t)(m0+row)*lda + c);
                    if (n0 + row < N) vb = *(const float4*)(W + (size_t)(n0+row)*ldw + c);
                }
                ra[p*2+h] = va; rb[p*2+h] = vb;
            }
        }
    };
    auto STS = [&](int buf){
        __nv_bfloat16* base = sm + buf*4*PLANEn;
#pragma unroll
        for (int p=0;p<2;p++){
            int row = lr + p*64;
            int bo = row*40 + lc*8;
            uint4 hi, lo;
            split8(ra[p*2], ra[p*2+1], hi, lo);
            *(uint4*)(base + bo) = hi;
            *(uint4*)(base + PLANEn + bo) = lo;
            split8(rb[p*2], rb[p*2+1], hi, lo);
            *(uint4*)(base + 2*PLANEn + bo) = hi;
            *(uint4*)(base + 3*PLANEn + bo) = lo;
        }
    };
    auto COMP = [&](int buf){
        __nv_bfloat16* Ah = sm + buf*4*PLANEn;
        __nv_bfloat16* Al = Ah + PLANEn;
        __nv_bfloat16* Bh = Ah + 2*PLANEn;
        __nv_bfloat16* Bl = Ah + 3*PLANEn;
#pragma unroll
        for (int kk=0; kk<2; kk++){
            uint32_t ah[2][4], al[2][4];
#pragma unroll
            for (int i=0;i<2;i++){
                int arow = warp_m*32 + i*16 + (lid & 15);
                int acol = kk*16 + (lid >> 4)*8;
                ldm_x4(ah[i], sptr(Ah + arow*40 + acol));
                ldm_x4(al[i], sptr(Al + arow*40 + acol));
            }
#pragma unroll
            for (int jp=0; jp<4; jp++){
                uint32_t bh[4], bl[4];
                int brow = warp_n*64 + jp*16 + ((lid >> 4) << 3) + (lid & 7);
                int bcol = kk*16 + ((lid >> 3) & 1)*8;
                ldm_x4(bh, sptr(Bh + brow*40 + bcol));
                ldm_x4(bl, sptr(Bl + brow*40 + bcol));
#pragma unroll
                for (int i=0;i<2;i++){
                    mma_bf16(acc[i][jp*2],   ah[i], &bh[0]);
                    mma_bf16(acc[i][jp*2],   al[i], &bh[0]);
                    mma_bf16(acc[i][jp*2],   ah[i], &bl[0]);
                    mma_bf16(acc[i][jp*2+1], ah[i], &bh[2]);
                    mma_bf16(acc[i][jp*2+1], al[i], &bh[2]);
                    mma_bf16(acc[i][jp*2+1], ah[i], &bl[2]);
                }
            }
        }
    };

    LD(0); STS(0); __syncthreads();
    const int nkc = Kloop >> 5;
    for (int kc = 0; kc < nkc; kc++){
        bool more = (kc + 1) < nkc;
        if (more) LD((kc+1) << 5);
        COMP(kc & 1);
        if (more){
            STS((kc+1) & 1);
            __syncthreads();
        }
    }

#pragma unroll
    for (int i=0;i<2;i++){
#pragma unroll
        for (int j=0;j<8;j++){
            int r = m0 + warp_m*32 + i*16 + (lid >> 2);
            int c = n0 + warp_n*64 + j*8 + (lid & 3)*2;
            if (c < N){
                float b0 = 0.f, b1 = 0.f;
                if (EPI >= 1){ b0 = bias[c]; b1 = bias[c+1]; }
                float v0 = acc[i][j][0] + b0, v1 = acc[i][j][1] + b1;
                float v2 = acc[i][j][2] + b0, v3 = acc[i][j][3] + b1;
                if (EPI == 2){
                    v0 = (v0 >= 0.f) ? v0 : 0.2f*v0;
                    v1 = (v1 >= 0.f) ? v1 : 0.2f*v1;
                    v2 = (v2 >= 0.f) ? v2 : 0.2f*v2;
                    v3 = (v3 >= 0.f) ? v3 : 0.2f*v3;
                }
                if (EPI == 3){
                    v0 = softplus_f(v0); v1 = softplus_f(v1);
                    v2 = softplus_f(v2); v3 = softplus_f(v3);
                }
                if (r < M)     *(float2*)(Co + (size_t)r*N + c)     = make_float2(v0, v1);
                if (r + 8 < M) *(float2*)(Co + (size_t)(r+8)*N + c) = make_float2(v2, v3);
            }
        }
    }
}
#define SMEM_G2 (2*4*PLANEn*2)   // 81920 bytes

// ---------------- token assembly ----------------
__global__ void assemble_kernel(const float* __restrict__ img,
                                const float* __restrict__ lid,
                                const float* __restrict__ rad,
                                const float* __restrict__ gps,
                                const float* __restrict__ pos)
{
    int c = threadIdx.x;
    int t = blockIdx.x;
    int b = blockIdx.y;
    float v;
    if (t < 960){
        int q = t >> 6, p = t & 63;
        int grp = q / 5, s = q - grp*5;
        int band = c >> 7;
        int code = grp + band; if (code >= 3) code -= 3;
        const float* sel = (code == 0) ? img : (code == 1) ? lid : rad;
        v = sel[((size_t)((b*5 + s)*384 + c) << 6) + p];
    } else {
        v = gps[((size_t)(b*2 + (t-960)))*384 + c];
    }
    g_X[((size_t)(b*TTn + t))*CCn + c] = v + pos[t*CCn + c];
}

// ---------------- LayerNorm ----------------
__global__ void ln_kernel(const float* __restrict__ x, const float* __restrict__ gam,
                          const float* __restrict__ bet, float* __restrict__ out)
{
    int m = blockIdx.x, tid = threadIdx.x;
    const float* row = x + (size_t)m*CCn;
    float v0 = row[tid], v1 = row[tid+128], v2 = row[tid+256];
    float s = v0+v1+v2;
    float q = v0*v0 + v1*v1 + v2*v2;
#pragma unroll
    for (int off=16; off; off>>=1){
        s += __shfl_xor_sync(0xffffffffu, s, off);
        q += __shfl_xor_sync(0xffffffffu, q, off);
    }
    __shared__ float ss[4], sq[4];
    if ((tid & 31) == 0){ ss[tid>>5] = s; sq[tid>>5] = q; }
    __syncthreads();
    s = ss[0]+ss[1]+ss[2]+ss[3];
    q = sq[0]+sq[1]+sq[2]+sq[3];
    float mean = s * (1.0f/384.0f);
    float var  = q * (1.0f/384.0f) - mean*mean;
    float rstd = rsqrtf(var + 1e-5f);
    float* orow = out + (size_t)m*CCn;
    orow[tid]     = (v0-mean)*rstd*gam[tid]     + bet[tid];
    orow[tid+128] = (v1-mean)*rstd*gam[tid+128] + bet[tid+128];
    orow[tid+256] = (v2-mean)*rstd*gam[tid+256] + bet[tid+256];
}

// ---------------- time-flip ----------------
__global__ void flip_kernel(){
    int idx = blockIdx.x*blockDim.x + threadIdx.x;
    if (idx >= MMn*96) return;
    int row = idx / 96, c4 = idx - row*96;
    int b = row / TTn, t = row - b*TTn;
    ((float4*)g_XFLIP)[idx] =
        ((const float4*)g_XFC1)[(size_t)(b*TTn + (TTn-1-t))*96 + c4];
}

// ---------------- depthwise causal conv + SiLU (float4 over d) ----------------
__global__ void conv_silu4_kernel(const float* __restrict__ cw, const float* __restrict__ cb){
    int idx = blockIdx.x*blockDim.x + threadIdx.x;   // over MMn*192
    if (idx >= MMn*(DIn/4)) return;
    int d4 = (idx % (DIn/4))*4;
    int m = idx / (DIn/4);
    int b = m / TTn;
    int t = m - b*TTn;
    const float* base = g_XZ + (size_t)(b*TTn)*(2*DIn) + d4;
    float4 w0 = *(const float4*)(cw + (size_t)(d4+0)*4);
    float4 w1 = *(const float4*)(cw + (size_t)(d4+1)*4);
    float4 w2 = *(const float4*)(cw + (size_t)(d4+2)*4);
    float4 w3 = *(const float4*)(cw + (size_t)(d4+3)*4);
    float4 acc = *(const float4*)(cb + d4);
    if (t >= 3){
        float4 v = *(const float4*)(base + (size_t)(t-3)*(2*DIn));
        acc.x = fmaf(w0.x, v.x, acc.x); acc.y = fmaf(w1.x, v.y, acc.y);
        acc.z = fmaf(w2.x, v.z, acc.z); acc.w = fmaf(w3.x, v.w, acc.w);
    }
    if (t >= 2){
        float4 v = *(const float4*)(base + (size_t)(t-2)*(2*DIn));
        acc.x = fmaf(w0.y, v.x, acc.x); acc.y = fmaf(w1.y, v.y, acc.y);
        acc.z = fmaf(w2.y, v.z, acc.z); acc.w = fmaf(w3.y, v.w, acc.w);
    }
    if (t >= 1){
        float4 v = *(const float4*)(base + (size_t)(t-1)*(2*DIn));
        acc.x = fmaf(w0.z, v.x, acc.x); acc.y = fmaf(w1.z, v.y, acc.y);
        acc.z = fmaf(w2.z, v.z, acc.z); acc.w = fmaf(w3.z, v.w, acc.w);
    }
    {
        float4 v = *(const float4*)(base + (size_t)t*(2*DIn));
        acc.x = fmaf(w0.w, v.x, acc.x); acc.y = fmaf(w1.w, v.y, acc.y);
        acc.z = fmaf(w2.w, v.z, acc.z); acc.w = fmaf(w3.w, v.w, acc.w);
    }
    float4 o;
    o.x = silu_f(acc.x); o.y = silu_f(acc.y); o.z = silu_f(acc.z); o.w = silu_f(acc.w);
    *(float4*)(g_XCONV + (size_t)m*DIn + d4) = o;
}

// ---------------- selective scan v2: smem-staged, double-buffered ----------------
// grid (24,16), 128 threads. Block owns 32 d-channels of one batch.
// Thread: quad q=tid>>2 -> d = d0+q; lane=tid&3 -> states [lane*4, lane*4+4).
__global__ void __launch_bounds__(128)
scan2_kernel(const float* __restrict__ a_log, const float* __restrict__ Dp){
    __shared__ float sDT[2][16][32], sXc[2][16][32], sZc[2][16][32], sBC[2][16][32];
    __shared__ float sY[16][32];

    const int tid = threadIdx.x;
    const int q = tid >> 2, lane = tid & 3;
    const int b = blockIdx.y;
    const int d0 = blockIdx.x * 32;
    const int d = d0 + q;
    const int mb = b * TTn;

    float4 av = *(const float4*)(a_log + (size_t)d*16 + lane*4);
    float cA[4] = { -fexp(av.x)*1.4426950408889634f, -fexp(av.y)*1.4426950408889634f,
                    -fexp(av.z)*1.4426950408889634f, -fexp(av.w)*1.4426950408889634f };
    float h[4] = {0.f,0.f,0.f,0.f};
    float Dv = Dp[d];

    const int tld = tid >> 3;      // 0..15 (timestep row this thread loads)
    const int fld = tid & 7;       // 0..7  (float4 column)
    float4 rDT, rX, rZ, rBC;

    auto LDc = [&](int c){
        int t = c*16 + tld;
        if (t < TTn){
            size_t m = (size_t)(mb + t);
            rDT = *(const float4*)(g_DT    + m*DIn + d0 + fld*4);
            rX  = *(const float4*)(g_XCONV + m*DIn + d0 + fld*4);
            rZ  = *(const float4*)(g_XZ    + m*(2*DIn) + DIn + d0 + fld*4);
            rBC = *(const float4*)(g_XDBL  + m*XPn + 24 + fld*4);
        } else {
            rDT = rX = rZ = rBC = make_float4(0,0,0,0);
        }
    };
    auto STSc = [&](int buf){
        *(float4*)&sDT[buf][tld][fld*4] = rDT;
        *(float4*)&sXc[buf][tld][fld*4] = rX;
        *(float4*)&sZc[buf][tld][fld*4] = rZ;
        *(float4*)&sBC[buf][tld][fld*4] = rBC;
    };

    const int nch = (TTn + 15) >> 4;   // 61
    LDc(0); STSc(0); __syncthreads();

    for (int c = 0; c < nch; c++){
        int buf = c & 1;
        bool more = (c + 1) < nch;
        if (more) LDc(c + 1);
        int rem = TTn - c*16; if (rem > 16) rem = 16;

        for (int tt = 0; tt < rem; tt++){
            float dtv = sDT[buf][tt][q];
            float xv  = sXc[buf][tt][q];
            float4 Bv = *(float4*)&sBC[buf][tt][lane*4];
            float4 Cv = *(float4*)&sBC[buf][tt][16 + lane*4];
            float Bj[4] = {Bv.x, Bv.y, Bv.z, Bv.w};
            float Cj[4] = {Cv.x, Cv.y, Cv.z, Cv.w};
            float dtx = dtv * xv;
            float y = 0.f;
#pragma unroll
            for (int j = 0; j < 4; j++){
                float a = fexp2(dtv * cA[j]);
                h[j] = fmaf(h[j], a, dtx * Bj[j]);
                y    = fmaf(h[j], Cj[j], y);
            }
            y += __shfl_xor_sync(0xffffffffu, y, 1);
            y += __shfl_xor_sync(0xffffffffu, y, 2);
            if (lane == 0) sY[tt][q] = fmaf(Dv, xv, y);
        }
        __syncthreads();
        // epilogue: y * silu(z), coalesced float4 store
        if (tld < rem){
            float4 yv = *(float4*)&sY[tld][fld*4];
            float4 zv = *(float4*)&sZc[buf][tld][fld*4];
            yv.x *= silu_f(zv.x); yv.y *= silu_f(zv.y);
            yv.z *= silu_f(zv.z); yv.w *= silu_f(zv.w);
            *(float4*)(g_Y + (size_t)(mb + c*16 + tld)*DIn + d0 + fld*4) = yv;
        }
        if (more){
            STSc(buf ^ 1);
            __syncthreads();
        }
    }
}

// ---------------- combine ----------------
__global__ void combine_kernel(){
    int idx = blockIdx.x*blockDim.x + threadIdx.x;
    if (idx >= MMn*96) return;
    float4 bm = ((const float4*)g_BM)[idx];
    float4 fm = ((const float4*)g_FM)[idx];
    float4 rl = ((const float4*)g_RELU)[idx];
    float4 o;
    o.x = bm.x*(rl.x+fm.x);
    o.y = bm.y*(rl.y+fm.y);
    o.z = bm.z*(rl.z+fm.z);
    o.w = bm.w*(rl.w+fm.w);
    ((float4*)g_X)[idx] = o;
}

// ---------------- final LN + scatter ----------------
__global__ void final_kernel(const float* __restrict__ gam, const float* __restrict__ bet,
                             float* __restrict__ out)
{
    int m = blockIdx.x, tid = threadIdx.x;
    int b = m / TTn, t = m - b*TTn;
    const float* row = g_X + (size_t)m*CCn;
    float v0 = row[tid], v1 = row[tid+128], v2 = row[tid+256];
    float s = v0+v1+v2;
    float q = v0*v0 + v1*v1 + v2*v2;
#pragma unroll
    for (int off=16; off; off>>=1){
        s += __shfl_xor_sync(0xffffffffu, s, off);
        q += __shfl_xor_sync(0xffffffffu, q, off);
    }
    __shared__ float ss[4], sq[4];
    if ((tid & 31) == 0){ ss[tid>>5] = s; sq[tid>>5] = q; }
    __syncthreads();
    s = ss[0]+ss[1]+ss[2]+ss[3];
    q = sq[0]+sq[1]+sq[2]+sq[3];
    float mean = s * (1.0f/384.0f);
    float var  = q * (1.0f/384.0f) - mean*mean;
    float rstd = rsqrtf(var + 1e-5f);
    float vs[3] = {v0, v1, v2};
#pragma unroll
    for (int i=0;i<3;i++){
        int c = tid + i*128;
        float val = (vs[i]-mean)*rstd*gam[c] + bet[c];
        size_t dst;
        if (t < 960){
            int qq = t >> 6, p = t & 63;
            int sec = qq / 5, sidx = qq - sec*5;
            dst = (size_t)sec*IMG_BLK + (((size_t)((b*5+sidx)*384 + c)) << 6) + p;
        } else {
            dst = (size_t)3*IMG_BLK + (size_t)(b*2 + (t-960))*384 + c;
        }
        out[dst] = val;
    }
}

// ---------------- launch ----------------
extern "C" void kernel_launch(void* const* d_in, const int* in_sizes, int n_in,
                              void* d_out, int out_size)
{
    const float* img      = (const float*)d_in[0];
    const float* lid      = (const float*)d_in[1];
    const float* rad      = (const float*)d_in[2];
    const float* gps      = (const float*)d_in[3];
    const float* pos      = (const float*)d_in[4];
    const float* ln1_g    = (const float*)d_in[5];
    const float* ln1_b    = (const float*)d_in[6];
    const float* fc1_w    = (const float*)d_in[7];
    const float* fc1_b    = (const float*)d_in[8];
    const float* fc2_w    = (const float*)d_in[9];
    const float* fc2_b    = (const float*)d_in[10];
    const float* in_proj_w= (const float*)d_in[11];
    const float* conv_w   = (const float*)d_in[12];
    const float* conv_b   = (const float*)d_in[13];
    const float* x_proj_w = (const float*)d_in[14];
    const float* dt_proj_w= (const float*)d_in[15];
    const float* dt_proj_b= (const float*)d_in[16];
    const float* A_log    = (const float*)d_in[17];
    const float* D_param  = (const float*)d_in[18];
    const float* out_proj_w=(const float*)d_in[19];
    const float* ln_f_g   = (const float*)d_in[20];
    const float* ln_f_b   = (const float*)d_in[21];

    float *pX, *pXLN, *pXFC1, *pXFLIP, *pXZ, *pXCONV, *pXDBL, *pDT, *pY, *pFM, *pBM, *pRELU;
    cudaGetSymbolAddress((void**)&pX,    g_X);
    cudaGetSymbolAddress((void**)&pXLN,  g_XLN);
    cudaGetSymbolAddress((void**)&pXFC1, g_XFC1);
    cudaGetSymbolAddress((void**)&pXFLIP,g_XFLIP);
    cudaGetSymbolAddress((void**)&pXZ,   g_XZ);
    cudaGetSymbolAddress((void**)&pXCONV,g_XCONV);
    cudaGetSymbolAddress((void**)&pXDBL, g_XDBL);
    cudaGetSymbolAddress((void**)&pDT,   g_DT);
    cudaGetSymbolAddress((void**)&pY,    g_Y);
    cudaGetSymbolAddress((void**)&pFM,   g_FM);
    cudaGetSymbolAddress((void**)&pBM,   g_BM);
    cudaGetSymbolAddress((void**)&pRELU, g_RELU);

    cudaFuncSetAttribute(mma_gemm2<0>, cudaFuncAttributeMaxDynamicSharedMemorySize, SMEM_G2);
    cudaFuncSetAttribute(mma_gemm2<1>, cudaFuncAttributeMaxDynamicSharedMemorySize, SMEM_G2);
    cudaFuncSetAttribute(mma_gemm2<2>, cudaFuncAttributeMaxDynamicSharedMemorySize, SMEM_G2);
    cudaFuncSetAttribute(mma_gemm2<3>, cudaFuncAttributeMaxDynamicSharedMemorySize, SMEM_G2);

    assemble_kernel<<<dim3(TTn, BZn), 384>>>(img, lid, rad, gps, pos);

    const int gm = (MMn + 127) / 128;              // 121
    const int EW = (MMn*96 + 255)/256;
    const int CW = (MMn*(DIn/4) + 255)/256;

    for (int l = 0; l < 4; l++){
        ln_kernel<<<MMn,128>>>(pX, ln1_g + l*CCn, ln1_b + l*CCn, pXLN);
        mma_gemm2<1><<<dim3(gm,3),256,SMEM_G2>>>(pXLN, CCn, fc1_w + (size_t)l*CCn*CCn, CCn,
                                                 fc1_b + l*CCn, pXFC1, MMn, CCn, CCn, CCn);
        flip_kernel<<<EW,256>>>();
        for (int dir = 0; dir < 2; dir++){
            int pd = l*2 + dir;
            const float* Ain = dir ? pXFLIP : pXFC1;
            mma_gemm2<0><<<dim3(gm,12),256,SMEM_G2>>>(Ain, CCn,
                                                      in_proj_w + (size_t)pd*2*DIn*CCn, CCn,
                                                      nullptr, pXZ, MMn, 2*DIn, CCn, CCn);
            conv_silu4_kernel<<<CW,256>>>(conv_w + (size_t)pd*DIn*4, conv_b + (size_t)pd*DIn);
            mma_gemm2<0><<<dim3(gm,1),256,SMEM_G2>>>(pXCONV, DIn,
                                                     x_proj_w + (size_t)pd*XPn*DIn, DIn,
                                                     nullptr, pXDBL, MMn, XPn, DIn, DIn);
            mma_gemm2<3><<<dim3(gm,6),256,SMEM_G2>>>(pXDBL, XPn,
                                                     dt_proj_w + (size_t)pd*DIn*DTRn, DTRn,
                                                     dt_proj_b + (size_t)pd*DIn, pDT,
                                                     MMn, DIn, 32, DTRn);
            scan2_kernel<<<dim3(24,BZn),128>>>(A_log + (size_t)pd*DIn*DSTn, D_param + (size_t)pd*DIn);
            mma_gemm2<0><<<dim3(gm,3),256,SMEM_G2>>>(pY, DIn,
                                                     out_proj_w + (size_t)pd*CCn*DIn, DIn,
                                                     nullptr, dir ? pBM : pFM, MMn, CCn, DIn, DIn);
        }
        mma_gemm2<2><<<dim3(gm,3),256,SMEM_G2>>>(pXFLIP, CCn, fc2_w + (size_t)l*CCn*CCn, CCn,
                                                 fc2_b + l*CCn, pRELU, MMn, CCn, CCn, CCn);
        combine_kernel<<<EW,256>>>();
    }

    final_kernel<<<MMn,128>>>(ln_f_g, ln_f_b, (float*)d_out);
}

// round 15
// speedup vs baseline: 2.4844x; 1.0964x over previous
#include <cuda_runtime.h>
#include <cuda_bf16.h>
#include <cstdint>

// ---------------- problem constants ----------------
#define BZn   16
#define TTn   962
#define CCn   384
#define DIn   768
#define DSTn  16
#define DTRn  24
#define XPn   56          // DTR + 2*DSTATE
#define MMn   (BZn*TTn)   // 15392
#define IMG_BLK 1966080   // 80*384*64

// ---------------- scratch (device globals; no allocation allowed) ----------------
__device__ __align__(16) float g_X    [MMn*CCn];
__device__ __align__(16) float g_XLN  [MMn*CCn];
__device__ __align__(16) float g_XFC1 [MMn*CCn];
__device__ __align__(16) float g_XFLIP[MMn*CCn];
__device__ __align__(16) float g_RELU [MMn*CCn];
// per-direction branch buffers (dir-major)
__device__ __align__(16) float g_XZ2   [2*(size_t)MMn*2*DIn];
__device__ __align__(16) float g_XCONV2[2*(size_t)MMn*DIn];
__device__ __align__(16) float g_XDBL2 [2*(size_t)MMn*XPn];
__device__ __align__(16) float g_DT2   [2*(size_t)MMn*DIn];
__device__ __align__(16) float g_Y2    [2*(size_t)MMn*DIn];
__device__ __align__(16) float g_FMBM  [2*(size_t)MMn*CCn];   // [0]=FM fwd, [1]=BM bwd

// ---------------- MUFU-free math helpers ----------------
__device__ __forceinline__ float fexp2(float y){
    y = fminf(fmaxf(y, -126.f), 126.f);
    float n = rintf(y);
    float f = y - n;
    float g = f * 0.69314718055994531f;
    float p = 1.98412698e-4f;
    p = fmaf(p, g, 1.38888889e-3f);
    p = fmaf(p, g, 8.33333333e-3f);
    p = fmaf(p, g, 4.16666667e-2f);
    p = fmaf(p, g, 1.66666667e-1f);
    p = fmaf(p, g, 0.5f);
    p = fmaf(p, g, 1.0f);
    p = fmaf(p, g, 1.0f);
    return p * __int_as_float(((int)n + 127) << 23);
}
__device__ __forceinline__ float fexp(float x){ return fexp2(x * 1.4426950408889634f); }
__device__ __forceinline__ float frcp_fast(float w){
    float r = __int_as_float(0x7EF311C3 - __float_as_int(w));
    r = r * fmaf(-w, r, 2.0f);
    r = r * fmaf(-w, r, 2.0f);
    r = r * fmaf(-w, r, 2.0f);
    return r;
}
__device__ __forceinline__ float silu_f(float x){ return x * frcp_fast(1.0f + fexp(-x)); }
__device__ __forceinline__ float softplus_f(float x){
    float ax = fabsf(x);
    float e  = fexp(-ax);
    float t  = e * frcp_fast(2.0f + e);
    float t2 = t * t;
    float p  = 2.0f/9.0f;
    p = fmaf(p, t2, 2.0f/7.0f);
    p = fmaf(p, t2, 2.0f/5.0f);
    p = fmaf(p, t2, 2.0f/3.0f);
    p = fmaf(p, t2, 2.0f);
    return fmaxf(x, 0.0f) + p * t;
}

// ---------------- mma / ldmatrix helpers (non-'a' features, sm_80+) ----------------
__device__ __forceinline__ uint32_t sptr(const void* p){
    return (uint32_t)__cvta_generic_to_shared(p);
}
__device__ __forceinline__ void ldm_x4(uint32_t r[4], uint32_t addr){
    asm volatile("ldmatrix.sync.aligned.m8n8.x4.shared.b16 {%0,%1,%2,%3}, [%4];"
        : "=r"(r[0]), "=r"(r[1]), "=r"(r[2]), "=r"(r[3]) : "r"(addr));
}
__device__ __forceinline__ void mma_bf16(float* d, const uint32_t* a, const uint32_t* b){
    asm volatile("mma.sync.aligned.m16n8k16.row.col.f32.bf16.bf16.f32 "
        "{%0,%1,%2,%3}, {%4,%5,%6,%7}, {%8,%9}, {%0,%1,%2,%3};"
        : "+f"(d[0]), "+f"(d[1]), "+f"(d[2]), "+f"(d[3])
        : "r"(a[0]), "r"(a[1]), "r"(a[2]), "r"(a[3]), "r"(b[0]), "r"(b[1]));
}
__device__ __forceinline__ uint32_t pk2(float x, float y){
    __nv_bfloat162 t(__float2bfloat16(x), __float2bfloat16(y));
    return *reinterpret_cast<uint32_t*>(&t);
}
__device__ __forceinline__ void split8(const float4& a, const float4& b, uint4& hi, uint4& lo){
    float h0 = __bfloat162float(__float2bfloat16(a.x));
    float h1 = __bfloat162float(__float2bfloat16(a.y));
    float h2 = __bfloat162float(__float2bfloat16(a.z));
    float h3 = __bfloat162float(__float2bfloat16(a.w));
    float h4 = __bfloat162float(__float2bfloat16(b.x));
    float h5 = __bfloat162float(__float2bfloat16(b.y));
    float h6 = __bfloat162float(__float2bfloat16(b.z));
    float h7 = __bfloat162float(__float2bfloat16(b.w));
    hi.x = pk2(a.x, a.y); hi.y = pk2(a.z, a.w);
    hi.z = pk2(b.x, b.y); hi.w = pk2(b.z, b.w);
    lo.x = pk2(a.x - h0, a.y - h1); lo.y = pk2(a.z - h2, a.w - h3);
    lo.z = pk2(b.x - h4, b.y - h5); lo.w = pk2(b.z - h6, b.w - h7);
}

// ---------------- pipelined HMMA GEMM, bf16x3, dual-direction via blockIdx.z ------
// Co[m,n] = sum_k A[m,k]*W[n,k].  dir = blockIdx.z selects A0/A1, W += dir*wsz,
// Co += dir*csz, bias += dir*bsz.
// EPI: 0=none 1=bias 2=bias+leaky 3=bias+softplus 4=bias + dual store (Co + time-flipped Co2)
#define PLANEn (128*40)
template<int EPI>
__global__ void __launch_bounds__(256)
mma_gemm3(const float* __restrict__ A0, const float* __restrict__ A1, int lda,
          const float* __restrict__ W, int ldw, size_t wsz,
          const float* __restrict__ bias, size_t bsz,
          float* __restrict__ Co, size_t csz, float* __restrict__ Co2,
          int M, int N, int Kloop, int Klim)
{
    extern __shared__ __align__(16) __nv_bfloat16 sm[];

    const int dir = blockIdx.z;
    const float* A = dir ? A1 : A0;
    W  += (size_t)dir * wsz;
    Co += (size_t)dir * csz;
    if (EPI >= 1) bias += (size_t)dir * bsz;

    const int tid = threadIdx.x;
    const int lid = tid & 31, wid = tid >> 5;
    const int warp_m = wid & 3, warp_n = wid >> 2;
    const int m0 = blockIdx.x * 128, n0 = blockIdx.y * 128;
    const int lr = tid >> 2, lc = tid & 3;

    float acc[2][8][4];
#pragma unroll
    for (int i=0;i<2;i++)
#pragma unroll
        for (int j=0;j<8;j++)
#pragma unroll
            for (int q=0;q<4;q++) acc[i][j][q] = 0.f;

    float4 ra[4], rb[4];

    auto LD = [&](int kb){
#pragma unroll
        for (int p=0;p<2;p++){
            int row = lr + p*64;
#pragma unroll
            for (int h=0;h<2;h++){
                int c = kb + lc*8 + h*4;
                float4 va = make_float4(0,0,0,0), vb = make_float4(0,0,0,0);
                if (c + 3 < Klim){
                    if (m0 + row < M) va = *(const float4*)(A + (size_t)(m0+row)*lda + c);
                    if (n0 + row < N) vb = *(const float4*)(W + (size_t)(n0+row)*ldw + c);
                }
                ra[p*2+h] = va; rb[p*2+h] = vb;
            }
        }
    };
    auto STS = [&](int buf){
        __nv_bfloat16* base = sm + buf*4*PLANEn;
#pragma unroll
        for (int p=0;p<2;p++){
            int row = lr + p*64;
            int bo = row*40 + lc*8;
            uint4 hi, lo;
            split8(ra[p*2], ra[p*2+1], hi, lo);
            *(uint4*)(base + bo) = hi;
            *(uint4*)(base + PLANEn + bo) = lo;
            split8(rb[p*2], rb[p*2+1], hi, lo);
            *(uint4*)(base + 2*PLANEn + bo) = hi;
            *(uint4*)(base + 3*PLANEn + bo) = lo;
        }
    };
    auto COMP = [&](int buf){
        __nv_bfloat16* Ah = sm + buf*4*PLANEn;
        __nv_bfloat16* Al = Ah + PLANEn;
        __nv_bfloat16* Bh = Ah + 2*PLANEn;
        __nv_bfloat16* Bl = Ah + 3*PLANEn;
#pragma unroll
        for (int kk=0; kk<2; kk++){
            uint32_t ah[2][4], al[2][4];
#pragma unroll
            for (int i=0;i<2;i++){
                int arow = warp_m*32 + i*16 + (lid & 15);
                int acol = kk*16 + (lid >> 4)*8;
                ldm_x4(ah[i], sptr(Ah + arow*40 + acol));
                ldm_x4(al[i], sptr(Al + arow*40 + acol));
            }
#pragma unroll
            for (int jp=0; jp<4; jp++){
                uint32_t bh[4], bl[4];
                int brow = warp_n*64 + jp*16 + ((lid >> 4) << 3) + (lid & 7);
                int bcol = kk*16 + ((lid >> 3) & 1)*8;
                ldm_x4(bh, sptr(Bh + brow*40 + bcol));
                ldm_x4(bl, sptr(Bl + brow*40 + bcol));
#pragma unroll
                for (int i=0;i<2;i++){
                    mma_bf16(acc[i][jp*2],   ah[i], &bh[0]);
                    mma_bf16(acc[i][jp*2],   al[i], &bh[0]);
                    mma_bf16(acc[i][jp*2],   ah[i], &bl[0]);
                    mma_bf16(acc[i][jp*2+1], ah[i], &bh[2]);
                    mma_bf16(acc[i][jp*2+1], al[i], &bh[2]);
                    mma_bf16(acc[i][jp*2+1], ah[i], &bl[2]);
                }
            }
        }
    };

    LD(0); STS(0); __syncthreads();
    const int nkc = Kloop >> 5;
    for (int kc = 0; kc < nkc; kc++){
        bool more = (kc + 1) < nkc;
        if (more) LD((kc+1) << 5);
        COMP(kc & 1);
        if (more){
            STS((kc+1) & 1);
            __syncthreads();
        }
    }

#pragma unroll
    for (int i=0;i<2;i++){
#pragma unroll
        for (int j=0;j<8;j++){
            int r = m0 + warp_m*32 + i*16 + (lid >> 2);
            int c = n0 + warp_n*64 + j*8 + (lid & 3)*2;
            if (c < N){
                float b0 = 0.f, b1 = 0.f;
                if (EPI >= 1){ b0 = bias[c]; b1 = bias[c+1]; }
                float v0 = acc[i][j][0] + b0, v1 = acc[i][j][1] + b1;
                float v2 = acc[i][j][2] + b0, v3 = acc[i][j][3] + b1;
                if (EPI == 2){
                    v0 = (v0 >= 0.f) ? v0 : 0.2f*v0;
                    v1 = (v1 >= 0.f) ? v1 : 0.2f*v1;
                    v2 = (v2 >= 0.f) ? v2 : 0.2f*v2;
                    v3 = (v3 >= 0.f) ? v3 : 0.2f*v3;
                }
                if (EPI == 3){
                    v0 = softplus_f(v0); v1 = softplus_f(v1);
                    v2 = softplus_f(v2); v3 = softplus_f(v3);
                }
                if (r < M){
                    *(float2*)(Co + (size_t)r*N + c) = make_float2(v0, v1);
                    if (EPI == 4){
                        int bb = r / TTn, tt = r - bb*TTn;
                        int r2 = bb*TTn + (TTn-1 - tt);
                        *(float2*)(Co2 + (size_t)r2*N + c) = make_float2(v0, v1);
                    }
                }
                if (r + 8 < M){
                    *(float2*)(Co + (size_t)(r+8)*N + c) = make_float2(v2, v3);
                    if (EPI == 4){
                        int bb = (r+8) / TTn, tt = (r+8) - bb*TTn;
                        int r2 = bb*TTn + (TTn-1 - tt);
                        *(float2*)(Co2 + (size_t)r2*N + c) = make_float2(v2, v3);
                    }
                }
            }
        }
    }
}
#define SMEM_G2 (2*4*PLANEn*2)   // 81920 bytes

// ---------------- token assembly ----------------
__global__ void assemble_kernel(const float* __restrict__ img,
                                const float* __restrict__ lid,
                                const float* __restrict__ rad,
                                const float* __restrict__ gps,
                                const float* __restrict__ pos)
{
    int c = threadIdx.x;
    int t = blockIdx.x;
    int b = blockIdx.y;
    float v;
    if (t < 960){
        int q = t >> 6, p = t & 63;
        int grp = q / 5, s = q - grp*5;
        int band = c >> 7;
        int code = grp + band; if (code >= 3) code -= 3;
        const float* sel = (code == 0) ? img : (code == 1) ? lid : rad;
        v = sel[((size_t)((b*5 + s)*384 + c) << 6) + p];
    } else {
        v = gps[((size_t)(b*2 + (t-960)))*384 + c];
    }
    g_X[((size_t)(b*TTn + t))*CCn + c] = v + pos[t*CCn + c];
}

// ---------------- LayerNorm (standalone; used once on layer-0 input) -------------
__global__ void ln_kernel(const float* __restrict__ x, const float* __restrict__ gam,
                          const float* __restrict__ bet, float* __restrict__ out)
{
    int m = blockIdx.x, tid = threadIdx.x;
    const float* row = x + (size_t)m*CCn;
    float v0 = row[tid], v1 = row[tid+128], v2 = row[tid+256];
    float s = v0+v1+v2;
    float q = v0*v0 + v1*v1 + v2*v2;
#pragma unroll
    for (int off=16; off; off>>=1){
        s += __shfl_xor_sync(0xffffffffu, s, off);
        q += __shfl_xor_sync(0xffffffffu, q, off);
    }
    __shared__ float ss[4], sq[4];
    if ((tid & 31) == 0){ ss[tid>>5] = s; sq[tid>>5] = q; }
    __syncthreads();
    s = ss[0]+ss[1]+ss[2]+ss[3];
    q = sq[0]+sq[1]+sq[2]+sq[3];
    float mean = s * (1.0f/384.0f);
    float var  = q * (1.0f/384.0f) - mean*mean;
    float rstd = rsqrtf(var + 1e-5f);
    float* orow = out + (size_t)m*CCn;
    orow[tid]     = (v0-mean)*rstd*gam[tid]     + bet[tid];
    orow[tid+128] = (v1-mean)*rstd*gam[tid+128] + bet[tid+128];
    orow[tid+256] = (v2-mean)*rstd*gam[tid+256] + bet[tid+256];
}

// ---------------- depthwise causal conv + SiLU (float4 over d, dual-dir) ---------
__global__ void conv_silu4_kernel(const float* __restrict__ cwb, const float* __restrict__ cbb){
    int dir = blockIdx.y;
    const float* cw = cwb + (size_t)dir*DIn*4;
    const float* cb = cbb + (size_t)dir*DIn;
    const float* XZ = g_XZ2 + (size_t)dir*MMn*2*DIn;
    float* XC = g_XCONV2 + (size_t)dir*MMn*DIn;

    int idx = blockIdx.x*blockDim.x + threadIdx.x;
    if (idx >= MMn*(DIn/4)) return;
    int d4 = (idx % (DIn/4))*4;
    int m = idx / (DIn/4);
    int b = m / TTn;
    int t = m - b*TTn;
    const float* base = XZ + (size_t)(b*TTn)*(2*DIn) + d4;
    float4 w0 = *(const float4*)(cw + (size_t)(d4+0)*4);
    float4 w1 = *(const float4*)(cw + (size_t)(d4+1)*4);
    float4 w2 = *(const float4*)(cw + (size_t)(d4+2)*4);
    float4 w3 = *(const float4*)(cw + (size_t)(d4+3)*4);
    float4 acc = *(const float4*)(cb + d4);
    if (t >= 3){
        float4 v = *(const float4*)(base + (size_t)(t-3)*(2*DIn));
        acc.x = fmaf(w0.x, v.x, acc.x); acc.y = fmaf(w1.x, v.y, acc.y);
        acc.z = fmaf(w2.x, v.z, acc.z); acc.w = fmaf(w3.x, v.w, acc.w);
    }
    if (t >= 2){
        float4 v = *(const float4*)(base + (size_t)(t-2)*(2*DIn));
        acc.x = fmaf(w0.y, v.x, acc.x); acc.y = fmaf(w1.y, v.y, acc.y);
        acc.z = fmaf(w2.y, v.z, acc.z); acc.w = fmaf(w3.y, v.w, acc.w);
    }
    if (t >= 1){
        float4 v = *(const float4*)(base + (size_t)(t-1)*(2*DIn));
        acc.x = fmaf(w0.z, v.x, acc.x); acc.y = fmaf(w1.z, v.y, acc.y);
        acc.z = fmaf(w2.z, v.z, acc.z); acc.w = fmaf(w3.z, v.w, acc.w);
    }
    {
        float4 v = *(const float4*)(base + (size_t)t*(2*DIn));
        acc.x = fmaf(w0.w, v.x, acc.x); acc.y = fmaf(w1.w, v.y, acc.y);
        acc.z = fmaf(w2.w, v.z, acc.z); acc.w = fmaf(w3.w, v.w, acc.w);
    }
    float4 o;
    o.x = silu_f(acc.x); o.y = silu_f(acc.y); o.z = silu_f(acc.z); o.w = silu_f(acc.w);
    *(float4*)(XC + (size_t)m*DIn + d4) = o;
}

// ---------------- selective scan: smem-staged, double-buffered, dual-dir ---------
// grid (24, 16, 2), 128 threads. Block owns 32 d-channels of one batch, one dir.
__global__ void __launch_bounds__(128)
scan2_kernel(const float* __restrict__ a_logb, const float* __restrict__ Dpb){
    __shared__ float sDT[2][16][32], sXc[2][16][32], sZc[2][16][32], sBC[2][16][32];
    __shared__ float sY[16][32];

    const int dir = blockIdx.z;
    const float* a_log = a_logb + (size_t)dir*DIn*DSTn;
    const float* Dp    = Dpb   + (size_t)dir*DIn;
    const float* DT  = g_DT2   + (size_t)dir*MMn*DIn;
    const float* XC  = g_XCONV2+ (size_t)dir*MMn*DIn;
    const float* XZ  = g_XZ2   + (size_t)dir*MMn*2*DIn;
    const float* XD  = g_XDBL2 + (size_t)dir*MMn*XPn;
    float*       Y   = g_Y2    + (size_t)dir*MMn*DIn;

    const int tid = threadIdx.x;
    const int q = tid >> 2, lane = tid & 3;
    const int b = blockIdx.y;
    const int d0 = blockIdx.x * 32;
    const int d = d0 + q;
    const int mb = b * TTn;

    float4 av = *(const float4*)(a_log + (size_t)d*16 + lane*4);
    float cA[4] = { -fexp(av.x)*1.4426950408889634f, -fexp(av.y)*1.4426950408889634f,
                    -fexp(av.z)*1.4426950408889634f, -fexp(av.w)*1.4426950408889634f };
    float h[4] = {0.f,0.f,0.f,0.f};
    float Dv = Dp[d];

    const int tld = tid >> 3;
    const int fld = tid & 7;
    float4 rDT, rX, rZ, rBC;

    auto LDc = [&](int c){
        int t = c*16 + tld;
        if (t < TTn){
            size_t m = (size_t)(mb + t);
            rDT = *(const float4*)(DT + m*DIn + d0 + fld*4);
            rX  = *(const float4*)(XC + m*DIn + d0 + fld*4);
            rZ  = *(const float4*)(XZ + m*(2*DIn) + DIn + d0 + fld*4);
            rBC = *(const float4*)(XD + m*XPn + 24 + fld*4);
        } else {
            rDT = rX = rZ = rBC = make_float4(0,0,0,0);
        }
    };
    auto STSc = [&](int buf){
        *(float4*)&sDT[buf][tld][fld*4] = rDT;
        *(float4*)&sXc[buf][tld][fld*4] = rX;
        *(float4*)&sZc[buf][tld][fld*4] = rZ;
        *(float4*)&sBC[buf][tld][fld*4] = rBC;
    };

    const int nch = (TTn + 15) >> 4;   // 61
    LDc(0); STSc(0); __syncthreads();

    for (int c = 0; c < nch; c++){
        int buf = c & 1;
        bool more = (c + 1) < nch;
        if (more) LDc(c + 1);
        int rem = TTn - c*16; if (rem > 16) rem = 16;

        for (int tt = 0; tt < rem; tt++){
            float dtv = sDT[buf][tt][q];
            float xv  = sXc[buf][tt][q];
            float4 Bv = *(float4*)&sBC[buf][tt][lane*4];
            float4 Cv = *(float4*)&sBC[buf][tt][16 + lane*4];
            float Bj[4] = {Bv.x, Bv.y, Bv.z, Bv.w};
            float Cj[4] = {Cv.x, Cv.y, Cv.z, Cv.w};
            float dtx = dtv * xv;
            float y = 0.f;
#pragma unroll
            for (int j = 0; j < 4; j++){
                float a = fexp2(dtv * cA[j]);
                h[j] = fmaf(h[j], a, dtx * Bj[j]);
                y    = fmaf(h[j], Cj[j], y);
            }
            y += __shfl_xor_sync(0xffffffffu, y, 1);
            y += __shfl_xor_sync(0xffffffffu, y, 2);
            if (lane == 0) sY[tt][q] = fmaf(Dv, xv, y);
        }
        __syncthreads();
        if (tld < rem){
            float4 yv = *(float4*)&sY[tld][fld*4];
            float4 zv = *(float4*)&sZc[buf][tld][fld*4];
            yv.x *= silu_f(zv.x); yv.y *= silu_f(zv.y);
            yv.z *= silu_f(zv.z); yv.w *= silu_f(zv.w);
            *(float4*)(Y + (size_t)(mb + c*16 + tld)*DIn + d0 + fld*4) = yv;
        }
        if (more){
            STSc(buf ^ 1);
            __syncthreads();
        }
    }
}

// ---------------- fused combine + LayerNorm ----------------
// X = BM*(RELU+FM); XLN = LN(X) with next layer's gamma/beta.
__global__ void combine_ln_kernel(const float* __restrict__ gam, const float* __restrict__ bet)
{
    int m = blockIdx.x, tid = threadIdx.x;
    float v[3];
#pragma unroll
    for (int i=0;i<3;i++){
        int c = tid + i*128;
        size_t o = (size_t)m*CCn + c;
        float fm = g_FMBM[o];
        float bm = g_FMBM[(size_t)MMn*CCn + o];
        float rl = g_RELU[o];
        v[i] = bm*(rl + fm);
        g_X[o] = v[i];
    }
    float s = v[0]+v[1]+v[2];
    float q = v[0]*v[0] + v[1]*v[1] + v[2]*v[2];
#pragma unroll
    for (int off=16; off; off>>=1){
        s += __shfl_xor_sync(0xffffffffu, s, off);
        q += __shfl_xor_sync(0xffffffffu, q, off);
    }
    __shared__ float ss[4], sq[4];
    if ((tid & 31) == 0){ ss[tid>>5] = s; sq[tid>>5] = q; }
    __syncthreads();
    s = ss[0]+ss[1]+ss[2]+ss[3];
    q = sq[0]+sq[1]+sq[2]+sq[3];
    float mean = s * (1.0f/384.0f);
    float var  = q * (1.0f/384.0f) - mean*mean;
    float rstd = rsqrtf(var + 1e-5f);
#pragma unroll
    for (int i=0;i<3;i++){
        int c = tid + i*128;
        g_XLN[(size_t)m*CCn + c] = (v[i]-mean)*rstd*gam[c] + bet[c];
    }
}

// ---------------- final LN + scatter ----------------
__global__ void final_kernel(const float* __restrict__ gam, const float* __restrict__ bet,
                             float* __restrict__ out)
{
    int m = blockIdx.x, tid = threadIdx.x;
    int b = m / TTn, t = m - b*TTn;
    const float* row = g_X + (size_t)m*CCn;
    float v0 = row[tid], v1 = row[tid+128], v2 = row[tid+256];
    float s = v0+v1+v2;
    float q = v0*v0 + v1*v1 + v2*v2;
#pragma unroll
    for (int off=16; off; off>>=1){
        s += __shfl_xor_sync(0xffffffffu, s, off);
        q += __shfl_xor_sync(0xffffffffu, q, off);
    }
    __shared__ float ss[4], sq[4];
    if ((tid & 31) == 0){ ss[tid>>5] = s; sq[tid>>5] = q; }
    __syncthreads();
    s = ss[0]+ss[1]+ss[2]+ss[3];
    q = sq[0]+sq[1]+sq[2]+sq[3];
    float mean = s * (1.0f/384.0f);
    float var  = q * (1.0f/384.0f) - mean*mean;
    float rstd = rsqrtf(var + 1e-5f);
    float vs[3] = {v0, v1, v2};
#pragma unroll
    for (int i=0;i<3;i++){
        int c = tid + i*128;
        float val = (vs[i]-mean)*rstd*gam[c] + bet[c];
        size_t dst;
        if (t < 960){
            int qq = t >> 6, p = t & 63;
            int sec = qq / 5, sidx = qq - sec*5;
            dst = (size_t)sec*IMG_BLK + (((size_t)((b*5+sidx)*384 + c)) << 6) + p;
        } else {
            dst = (size_t)3*IMG_BLK + (size_t)(b*2 + (t-960))*384 + c;
        }
        out[dst] = val;
    }
}

// ---------------- launch ----------------
extern "C" void kernel_launch(void* const* d_in, const int* in_sizes, int n_in,
                              void* d_out, int out_size)
{
    const float* img      = (const float*)d_in[0];
    const float* lid      = (const float*)d_in[1];
    const float* rad      = (const float*)d_in[2];
    const float* gps      = (const float*)d_in[3];
    const float* pos      = (const float*)d_in[4];
    const float* ln1_g    = (const float*)d_in[5];
    const float* ln1_b    = (const float*)d_in[6];
    const float* fc1_w    = (const float*)d_in[7];
    const float* fc1_b    = (const float*)d_in[8];
    const float* fc2_w    = (const float*)d_in[9];
    const float* fc2_b    = (const float*)d_in[10];
    const float* in_proj_w= (const float*)d_in[11];
    const float* conv_w   = (const float*)d_in[12];
    const float* conv_b   = (const float*)d_in[13];
    const float* x_proj_w = (const float*)d_in[14];
    const float* dt_proj_w= (const float*)d_in[15];
    const float* dt_proj_b= (const float*)d_in[16];
    const float* A_log    = (const float*)d_in[17];
    const float* D_param  = (const float*)d_in[18];
    const float* out_proj_w=(const float*)d_in[19];
    const float* ln_f_g   = (const float*)d_in[20];
    const float* ln_f_b   = (const float*)d_in[21];

    float *pX, *pXLN, *pXFC1, *pXFLIP, *pRELU, *pXZ2, *pXCONV2, *pXDBL2, *pDT2, *pY2, *pFMBM;
    cudaGetSymbolAddress((void**)&pX,     g_X);
    cudaGetSymbolAddress((void**)&pXLN,   g_XLN);
    cudaGetSymbolAddress((void**)&pXFC1,  g_XFC1);
    cudaGetSymbolAddress((void**)&pXFLIP, g_XFLIP);
    cudaGetSymbolAddress((void**)&pRELU,  g_RELU);
    cudaGetSymbolAddress((void**)&pXZ2,   g_XZ2);
    cudaGetSymbolAddress((void**)&pXCONV2,g_XCONV2);
    cudaGetSymbolAddress((void**)&pXDBL2, g_XDBL2);
    cudaGetSymbolAddress((void**)&pDT2,   g_DT2);
    cudaGetSymbolAddress((void**)&pY2,    g_Y2);
    cudaGetSymbolAddress((void**)&pFMBM,  g_FMBM);

    cudaFuncSetAttribute(mma_gemm3<0>, cudaFuncAttributeMaxDynamicSharedMemorySize, SMEM_G2);
    cudaFuncSetAttribute(mma_gemm3<2>, cudaFuncAttributeMaxDynamicSharedMemorySize, SMEM_G2);
    cudaFuncSetAttribute(mma_gemm3<3>, cudaFuncAttributeMaxDynamicSharedMemorySize, SMEM_G2);
    cudaFuncSetAttribute(mma_gemm3<4>, cudaFuncAttributeMaxDynamicSharedMemorySize, SMEM_G2);

    assemble_kernel<<<dim3(TTn, BZn), 384>>>(img, lid, rad, gps, pos);
    ln_kernel<<<MMn,128>>>(pX, ln1_g, ln1_b, pXLN);

    const int gm = (MMn + 127) / 128;              // 121
    const int CW = (MMn*(DIn/4) + 255)/256;

    for (int l = 0; l < 4; l++){
        // fc1 (+bias) with fused time-flip: XLN -> XFC1 and XFLIP
        mma_gemm3<4><<<dim3(gm,3,1),256,SMEM_G2>>>(
            pXLN, pXLN, CCn, fc1_w + (size_t)l*CCn*CCn, CCn, 0,
            fc1_b + (size_t)l*CCn, 0, pXFC1, 0, pXFLIP, MMn, CCn, CCn, CCn);
        // in_proj, both dirs: A = XFC1 / XFLIP
        mma_gemm3<0><<<dim3(gm,12,2),256,SMEM_G2>>>(
            pXFC1, pXFLIP, CCn, in_proj_w + (size_t)l*2*2*DIn*CCn, CCn, (size_t)2*DIn*CCn,
            nullptr, 0, pXZ2, (size_t)MMn*2*DIn, nullptr, MMn, 2*DIn, CCn, CCn);
        conv_silu4_kernel<<<dim3(CW,2),256>>>(conv_w + (size_t)l*2*DIn*4,
                                              conv_b + (size_t)l*2*DIn);
        // x_proj, both dirs
        mma_gemm3<0><<<dim3(gm,1,2),256,SMEM_G2>>>(
            pXCONV2, pXCONV2 + (size_t)MMn*DIn, DIn,
            x_proj_w + (size_t)l*2*XPn*DIn, DIn, (size_t)XPn*DIn,
            nullptr, 0, pXDBL2, (size_t)MMn*XPn, nullptr, MMn, XPn, DIn, DIn);
        // dt_proj (+softplus), both dirs: K=24 padded to 32
        mma_gemm3<3><<<dim3(gm,6,2),256,SMEM_G2>>>(
            pXDBL2, pXDBL2 + (size_t)MMn*XPn, XPn,
            dt_proj_w + (size_t)l*2*DIn*DTRn, DTRn, (size_t)DIn*DTRn,
            dt_proj_b + (size_t)l*2*DIn, DIn, pDT2, (size_t)MMn*DIn, nullptr,
            MMn, DIn, 32, DTRn);
        scan2_kernel<<<dim3(24,BZn,2),128>>>(A_log + (size_t)l*2*DIn*DSTn,
                                             D_param + (size_t)l*2*DIn);
        // out_proj, both dirs -> FMBM[0]=FM, FMBM[1]=BM
        mma_gemm3<0><<<dim3(gm,3,2),256,SMEM_G2>>>(
            pY2, pY2 + (size_t)MMn*DIn, DIn,
            out_proj_w + (size_t)l*2*CCn*DIn, DIn, (size_t)CCn*DIn,
            nullptr, 0, pFMBM, (size_t)MMn*CCn, nullptr, MMn, CCn, DIn, DIn);
        // fc2 + leaky: XFLIP -> RELU
        mma_gemm3<2><<<dim3(gm,3,1),256,SMEM_G2>>>(
            pXFLIP, pXFLIP, CCn, fc2_w + (size_t)l*CCn*CCn, CCn, 0,
            fc2_b + (size_t)l*CCn, 0, pRELU, 0, nullptr, MMn, CCn, CCn, CCn);
        // combine + LN (next layer's params; harmless extra XLN on last layer)
        int ln_next = (l < 3) ? (l+1) : 3;
        combine_ln_kernel<<<MMn,128>>>(ln1_g + (size_t)ln_next*CCn,
                                       ln1_b + (size_t)ln_next*CCn);
    }

    final_kernel<<<MMn,128>>>(ln_f_g, ln_f_b, (float*)d_out);
}

// round 16
// speedup vs baseline: 2.6052x; 1.0486x over previous
#include <cuda_runtime.h>
#include <cuda_bf16.h>
#include <cstdint>

// ---------------- problem constants ----------------
#define BZn   16
#define TTn   962
#define CCn   384
#define DIn   768
#define DSTn  16
#define DTRn  24
#define XPn   56          // DTR + 2*DSTATE
#define MMn   (BZn*TTn)   // 15392
#define IMG_BLK 1966080   // 80*384*64

// ---------------- scratch (device globals; no allocation allowed) ----------------
__device__ __align__(16) float g_X    [MMn*CCn];
__device__ __align__(16) float g_XLN  [MMn*CCn];
__device__ __align__(16) float g_XFC1 [MMn*CCn];
__device__ __align__(16) float g_XFLIP[MMn*CCn];
__device__ __align__(16) float g_RELU [MMn*CCn];
// per-direction branch buffers (dir-major)
__device__ __align__(16) float g_XZ2   [2*(size_t)MMn*2*DIn];
__device__ __align__(16) float g_XCONV2[2*(size_t)MMn*DIn];
__device__ __align__(16) float g_XDBL2 [2*(size_t)MMn*XPn];
__device__ __align__(16) float g_DT2   [2*(size_t)MMn*DIn];
__device__ __align__(16) float g_Y2    [2*(size_t)MMn*DIn];
__device__ __align__(16) float g_FMBM  [2*(size_t)MMn*CCn];   // [0]=FM fwd, [1]=BM bwd

// ---------------- MUFU-free math helpers ----------------
__device__ __forceinline__ float fexp2(float y){
    y = fminf(fmaxf(y, -126.f), 126.f);
    float n = rintf(y);
    float f = y - n;
    float g = f * 0.69314718055994531f;
    float p = 1.98412698e-4f;
    p = fmaf(p, g, 1.38888889e-3f);
    p = fmaf(p, g, 8.33333333e-3f);
    p = fmaf(p, g, 4.16666667e-2f);
    p = fmaf(p, g, 1.66666667e-1f);
    p = fmaf(p, g, 0.5f);
    p = fmaf(p, g, 1.0f);
    p = fmaf(p, g, 1.0f);
    return p * __int_as_float(((int)n + 127) << 23);
}
__device__ __forceinline__ float fexp(float x){ return fexp2(x * 1.4426950408889634f); }
__device__ __forceinline__ float frcp_fast(float w){
    float r = __int_as_float(0x7EF311C3 - __float_as_int(w));
    r = r * fmaf(-w, r, 2.0f);
    r = r * fmaf(-w, r, 2.0f);
    r = r * fmaf(-w, r, 2.0f);
    return r;
}
__device__ __forceinline__ float silu_f(float x){ return x * frcp_fast(1.0f + fexp(-x)); }
__device__ __forceinline__ float softplus_f(float x){
    float ax = fabsf(x);
    float e  = fexp(-ax);
    float t  = e * frcp_fast(2.0f + e);
    float t2 = t * t;
    float p  = 2.0f/9.0f;
    p = fmaf(p, t2, 2.0f/7.0f);
    p = fmaf(p, t2, 2.0f/5.0f);
    p = fmaf(p, t2, 2.0f/3.0f);
    p = fmaf(p, t2, 2.0f);
    return fmaxf(x, 0.0f) + p * t;
}

// ---------------- mma / ldmatrix helpers (non-'a' features, sm_80+) ----------------
__device__ __forceinline__ uint32_t sptr(const void* p){
    return (uint32_t)__cvta_generic_to_shared(p);
}
__device__ __forceinline__ void ldm_x4(uint32_t r[4], uint32_t addr){
    asm volatile("ldmatrix.sync.aligned.m8n8.x4.shared.b16 {%0,%1,%2,%3}, [%4];"
        : "=r"(r[0]), "=r"(r[1]), "=r"(r[2]), "=r"(r[3]) : "r"(addr));
}
__device__ __forceinline__ void mma_bf16(float* d, const uint32_t* a, const uint32_t* b){
    asm volatile("mma.sync.aligned.m16n8k16.row.col.f32.bf16.bf16.f32 "
        "{%0,%1,%2,%3}, {%4,%5,%6,%7}, {%8,%9}, {%0,%1,%2,%3};"
        : "+f"(d[0]), "+f"(d[1]), "+f"(d[2]), "+f"(d[3])
        : "r"(a[0]), "r"(a[1]), "r"(a[2]), "r"(a[3]), "r"(b[0]), "r"(b[1]));
}
__device__ __forceinline__ uint32_t pk2(float x, float y){
    __nv_bfloat162 t(__float2bfloat16(x), __float2bfloat16(y));
    return *reinterpret_cast<uint32_t*>(&t);
}
__device__ __forceinline__ void split8(const float4& a, const float4& b, uint4& hi, uint4& lo){
    float h0 = __bfloat162float(__float2bfloat16(a.x));
    float h1 = __bfloat162float(__float2bfloat16(a.y));
    float h2 = __bfloat162float(__float2bfloat16(a.z));
    float h3 = __bfloat162float(__float2bfloat16(a.w));
    float h4 = __bfloat162float(__float2bfloat16(b.x));
    float h5 = __bfloat162float(__float2bfloat16(b.y));
    float h6 = __bfloat162float(__float2bfloat16(b.z));
    float h7 = __bfloat162float(__float2bfloat16(b.w));
    hi.x = pk2(a.x, a.y); hi.y = pk2(a.z, a.w);
    hi.z = pk2(b.x, b.y); hi.w = pk2(b.z, b.w);
    lo.x = pk2(a.x - h0, a.y - h1); lo.y = pk2(a.z - h2, a.w - h3);
    lo.z = pk2(b.x - h4, b.y - h5); lo.w = pk2(b.z - h6, b.w - h7);
}

// ---------------- pipelined HMMA GEMM, bf16x3, dual-direction via blockIdx.z ------
// Co[m,n] = sum_k A[m,k]*W[n,k].  dir = blockIdx.z selects A0/A1, W += dir*wsz,
// Co += dir*csz, bias += dir*bsz.
// EPI: 0=none 1=bias 2=bias+leaky 3=bias+softplus 4=bias + dual store (Co + flipped Co2)
#define PLANEn (128*40)
template<int EPI>
__global__ void __launch_bounds__(256, 2)
mma_gemm3(const float* __restrict__ A0, const float* __restrict__ A1, int lda,
          const float* __restrict__ W, int ldw, size_t wsz,
          const float* __restrict__ bias, size_t bsz,
          float* __restrict__ Co, size_t csz, float* __restrict__ Co2,
          int M, int N, int Kloop, int Klim)
{
    extern __shared__ __align__(16) __nv_bfloat16 sm[];

    const int dir = blockIdx.z;
    const float* A = dir ? A1 : A0;
    W  += (size_t)dir * wsz;
    Co += (size_t)dir * csz;
    if (EPI >= 1) bias += (size_t)dir * bsz;

    const int tid = threadIdx.x;
    const int lid = tid & 31, wid = tid >> 5;
    const int warp_m = wid & 3, warp_n = wid >> 2;
    const int m0 = blockIdx.x * 128, n0 = blockIdx.y * 128;
    const int lr = tid >> 2, lc = tid & 3;

    float acc[2][8][4];
#pragma unroll
    for (int i=0;i<2;i++)
#pragma unroll
        for (int j=0;j<8;j++)
#pragma unroll
            for (int q=0;q<4;q++) acc[i][j][q] = 0.f;

    float4 ra[4], rb[4];

    auto LD = [&](int kb){
#pragma unroll
        for (int p=0;p<2;p++){
            int row = lr + p*64;
#pragma unroll
            for (int h=0;h<2;h++){
                int c = kb + lc*8 + h*4;
                float4 va = make_float4(0,0,0,0), vb = make_float4(0,0,0,0);
                if (c + 3 < Klim){
                    if (m0 + row < M) va = *(const float4*)(A + (size_t)(m0+row)*lda + c);
                    if (n0 + row < N) vb = *(const float4*)(W + (size_t)(n0+row)*ldw + c);
                }
                ra[p*2+h] = va; rb[p*2+h] = vb;
            }
        }
    };
    auto STS = [&](int buf){
        __nv_bfloat16* base = sm + buf*4*PLANEn;
#pragma unroll
        for (int p=0;p<2;p++){
            int row = lr + p*64;
            int bo = row*40 + lc*8;
            uint4 hi, lo;
            split8(ra[p*2], ra[p*2+1], hi, lo);
            *(uint4*)(base + bo) = hi;
            *(uint4*)(base + PLANEn + bo) = lo;
            split8(rb[p*2], rb[p*2+1], hi, lo);
            *(uint4*)(base + 2*PLANEn + bo) = hi;
            *(uint4*)(base + 3*PLANEn + bo) = lo;
        }
    };
    auto COMP = [&](int buf){
        __nv_bfloat16* Ah = sm + buf*4*PLANEn;
        __nv_bfloat16* Al = Ah + PLANEn;
        __nv_bfloat16* Bh = Ah + 2*PLANEn;
        __nv_bfloat16* Bl = Ah + 3*PLANEn;
#pragma unroll
        for (int kk=0; kk<2; kk++){
            uint32_t ah[2][4], al[2][4];
#pragma unroll
            for (int i=0;i<2;i++){
                int arow = warp_m*32 + i*16 + (lid & 15);
                int acol = kk*16 + (lid >> 4)*8;
                ldm_x4(ah[i], sptr(Ah + arow*40 + acol));
                ldm_x4(al[i], sptr(Al + arow*40 + acol));
            }
#pragma unroll
            for (int jp=0; jp<4; jp++){
                uint32_t bh[4], bl[4];
                int brow = warp_n*64 + jp*16 + ((lid >> 4) << 3) + (lid & 7);
                int bcol = kk*16 + ((lid >> 3) & 1)*8;
                ldm_x4(bh, sptr(Bh + brow*40 + bcol));
                ldm_x4(bl, sptr(Bl + brow*40 + bcol));
#pragma unroll
                for (int i=0;i<2;i++){
                    mma_bf16(acc[i][jp*2],   ah[i], &bh[0]);
                    mma_bf16(acc[i][jp*2],   al[i], &bh[0]);
                    mma_bf16(acc[i][jp*2],   ah[i], &bl[0]);
                    mma_bf16(acc[i][jp*2+1], ah[i], &bh[2]);
                    mma_bf16(acc[i][jp*2+1], al[i], &bh[2]);
                    mma_bf16(acc[i][jp*2+1], ah[i], &bl[2]);
                }
            }
        }
    };

    LD(0); STS(0); __syncthreads();
    const int nkc = Kloop >> 5;
    for (int kc = 0; kc < nkc; kc++){
        bool more = (kc + 1) < nkc;
        if (more) LD((kc+1) << 5);
        COMP(kc & 1);
        if (more){
            STS((kc+1) & 1);
            __syncthreads();
        }
    }

#pragma unroll
    for (int i=0;i<2;i++){
#pragma unroll
        for (int j=0;j<8;j++){
            int r = m0 + warp_m*32 + i*16 + (lid >> 2);
            int c = n0 + warp_n*64 + j*8 + (lid & 3)*2;
            if (c < N){
                float b0 = 0.f, b1 = 0.f;
                if (EPI >= 1){ b0 = bias[c]; b1 = bias[c+1]; }
                float v0 = acc[i][j][0] + b0, v1 = acc[i][j][1] + b1;
                float v2 = acc[i][j][2] + b0, v3 = acc[i][j][3] + b1;
                if (EPI == 2){
                    v0 = (v0 >= 0.f) ? v0 : 0.2f*v0;
                    v1 = (v1 >= 0.f) ? v1 : 0.2f*v1;
                    v2 = (v2 >= 0.f) ? v2 : 0.2f*v2;
                    v3 = (v3 >= 0.f) ? v3 : 0.2f*v3;
                }
                if (EPI == 3){
                    v0 = softplus_f(v0); v1 = softplus_f(v1);
                    v2 = softplus_f(v2); v3 = softplus_f(v3);
                }
                if (r < M){
                    *(float2*)(Co + (size_t)r*N + c) = make_float2(v0, v1);
                    if (EPI == 4){
                        int bb = r / TTn, tt = r - bb*TTn;
                        int r2 = bb*TTn + (TTn-1 - tt);
                        *(float2*)(Co2 + (size_t)r2*N + c) = make_float2(v0, v1);
                    }
                }
                if (r + 8 < M){
                    *(float2*)(Co + (size_t)(r+8)*N + c) = make_float2(v2, v3);
                    if (EPI == 4){
                        int bb = (r+8) / TTn, tt = (r+8) - bb*TTn;
                        int r2 = bb*TTn + (TTn-1 - tt);
                        *(float2*)(Co2 + (size_t)r2*N + c) = make_float2(v2, v3);
                    }
                }
            }
        }
    }
}
#define SMEM_G2 (2*4*PLANEn*2)   // 81920 bytes

// ---------------- token assembly ----------------
__global__ void assemble_kernel(const float* __restrict__ img,
                                const float* __restrict__ lid,
                                const float* __restrict__ rad,
                                const float* __restrict__ gps,
                                const float* __restrict__ pos)
{
    int c = threadIdx.x;
    int t = blockIdx.x;
    int b = blockIdx.y;
    float v;
    if (t < 960){
        int q = t >> 6, p = t & 63;
        int grp = q / 5, s = q - grp*5;
        int band = c >> 7;
        int code = grp + band; if (code >= 3) code -= 3;
        const float* sel = (code == 0) ? img : (code == 1) ? lid : rad;
        v = sel[((size_t)((b*5 + s)*384 + c) << 6) + p];
    } else {
        v = gps[((size_t)(b*2 + (t-960)))*384 + c];
    }
    g_X[((size_t)(b*TTn + t))*CCn + c] = v + pos[t*CCn + c];
}

// ---------------- LayerNorm (standalone; used once on layer-0 input) -------------
__global__ void ln_kernel(const float* __restrict__ x, const float* __restrict__ gam,
                          const float* __restrict__ bet, float* __restrict__ out)
{
    int m = blockIdx.x, tid = threadIdx.x;
    const float* row = x + (size_t)m*CCn;
    float v0 = row[tid], v1 = row[tid+128], v2 = row[tid+256];
    float s = v0+v1+v2;
    float q = v0*v0 + v1*v1 + v2*v2;
#pragma unroll
    for (int off=16; off; off>>=1){
        s += __shfl_xor_sync(0xffffffffu, s, off);
        q += __shfl_xor_sync(0xffffffffu, q, off);
    }
    __shared__ float ss[4], sq[4];
    if ((tid & 31) == 0){ ss[tid>>5] = s; sq[tid>>5] = q; }
    __syncthreads();
    s = ss[0]+ss[1]+ss[2]+ss[3];
    q = sq[0]+sq[1]+sq[2]+sq[3];
    float mean = s * (1.0f/384.0f);
    float var  = q * (1.0f/384.0f) - mean*mean;
    float rstd = rsqrtf(var + 1e-5f);
    float* orow = out + (size_t)m*CCn;
    orow[tid]     = (v0-mean)*rstd*gam[tid]     + bet[tid];
    orow[tid+128] = (v1-mean)*rstd*gam[tid+128] + bet[tid+128];
    orow[tid+256] = (v2-mean)*rstd*gam[tid+256] + bet[tid+256];
}

// ---------------- depthwise causal conv + SiLU (float4 over d, dual-dir) ---------
__global__ void conv_silu4_kernel(const float* __restrict__ cwb, const float* __restrict__ cbb){
    int dir = blockIdx.y;
    const float* cw = cwb + (size_t)dir*DIn*4;
    const float* cb = cbb + (size_t)dir*DIn;
    const float* XZ = g_XZ2 + (size_t)dir*MMn*2*DIn;
    float* XC = g_XCONV2 + (size_t)dir*MMn*DIn;

    int idx = blockIdx.x*blockDim.x + threadIdx.x;
    if (idx >= MMn*(DIn/4)) return;
    int d4 = (idx % (DIn/4))*4;
    int m = idx / (DIn/4);
    int b = m / TTn;
    int t = m - b*TTn;
    const float* base = XZ + (size_t)(b*TTn)*(2*DIn) + d4;
    float4 w0 = *(const float4*)(cw + (size_t)(d4+0)*4);
    float4 w1 = *(const float4*)(cw + (size_t)(d4+1)*4);
    float4 w2 = *(const float4*)(cw + (size_t)(d4+2)*4);
    float4 w3 = *(const float4*)(cw + (size_t)(d4+3)*4);
    float4 acc = *(const float4*)(cb + d4);
    if (t >= 3){
        float4 v = *(const float4*)(base + (size_t)(t-3)*(2*DIn));
        acc.x = fmaf(w0.x, v.x, acc.x); acc.y = fmaf(w1.x, v.y, acc.y);
        acc.z = fmaf(w2.x, v.z, acc.z); acc.w = fmaf(w3.x, v.w, acc.w);
    }
    if (t >= 2){
        float4 v = *(const float4*)(base + (size_t)(t-2)*(2*DIn));
        acc.x = fmaf(w0.y, v.x, acc.x); acc.y = fmaf(w1.y, v.y, acc.y);
        acc.z = fmaf(w2.y, v.z, acc.z); acc.w = fmaf(w3.y, v.w, acc.w);
    }
    if (t >= 1){
        float4 v = *(const float4*)(base + (size_t)(t-1)*(2*DIn));
        acc.x = fmaf(w0.z, v.x, acc.x); acc.y = fmaf(w1.z, v.y, acc.y);
        acc.z = fmaf(w2.z, v.z, acc.z); acc.w = fmaf(w3.z, v.w, acc.w);
    }
    {
        float4 v = *(const float4*)(base + (size_t)t*(2*DIn));
        acc.x = fmaf(w0.w, v.x, acc.x); acc.y = fmaf(w1.w, v.y, acc.y);
        acc.z = fmaf(w2.w, v.z, acc.z); acc.w = fmaf(w3.w, v.w, acc.w);
    }
    float4 o;
    o.x = silu_f(acc.x); o.y = silu_f(acc.y); o.z = silu_f(acc.z); o.w = silu_f(acc.w);
    *(float4*)(XC + (size_t)m*DIn + d4) = o;
}

// ---------------- selective scan: smem-staged, double-buffered, dual-dir ---------
// grid (24, 16, 2), 128 threads. Block owns 32 d-channels of one batch, one dir.
__global__ void __launch_bounds__(128)
scan2_kernel(const float* __restrict__ a_logb, const float* __restrict__ Dpb){
    __shared__ float sDT[2][16][32], sXc[2][16][32], sZc[2][16][32], sBC[2][16][32];
    __shared__ float sY[16][32];

    const int dir = blockIdx.z;
    const float* a_log = a_logb + (size_t)dir*DIn*DSTn;
    const float* Dp    = Dpb   + (size_t)dir*DIn;
    const float* DT  = g_DT2   + (size_t)dir*MMn*DIn;
    const float* XC  = g_XCONV2+ (size_t)dir*MMn*DIn;
    const float* XZ  = g_XZ2   + (size_t)dir*MMn*2*DIn;
    const float* XD  = g_XDBL2 + (size_t)dir*MMn*XPn;
    float*       Y   = g_Y2    + (size_t)dir*MMn*DIn;

    const int tid = threadIdx.x;
    const int q = tid >> 2, lane = tid & 3;
    const int b = blockIdx.y;
    const int d0 = blockIdx.x * 32;
    const int d = d0 + q;
    const int mb = b * TTn;

    float4 av = *(const float4*)(a_log + (size_t)d*16 + lane*4);
    float cA[4] = { -fexp(av.x)*1.4426950408889634f, -fexp(av.y)*1.4426950408889634f,
                    -fexp(av.z)*1.4426950408889634f, -fexp(av.w)*1.4426950408889634f };
    float h[4] = {0.f,0.f,0.f,0.f};
    float Dv = Dp[d];

    const int tld = tid >> 3;
    const int fld = tid & 7;
    float4 rDT, rX, rZ, rBC;

    auto LDc = [&](int c){
        int t = c*16 + tld;
        if (t < TTn){
            size_t m = (size_t)(mb + t);
            rDT = *(const float4*)(DT + m*DIn + d0 + fld*4);
            rX  = *(const float4*)(XC + m*DIn + d0 + fld*4);
            rZ  = *(const float4*)(XZ + m*(2*DIn) + DIn + d0 + fld*4);
            rBC = *(const float4*)(XD + m*XPn + 24 + fld*4);
        } else {
            rDT = rX = rZ = rBC = make_float4(0,0,0,0);
        }
    };
    auto STSc = [&](int buf){
        *(float4*)&sDT[buf][tld][fld*4] = rDT;
        *(float4*)&sXc[buf][tld][fld*4] = rX;
        *(float4*)&sZc[buf][tld][fld*4] = rZ;
        *(float4*)&sBC[buf][tld][fld*4] = rBC;
    };

    const int nch = (TTn + 15) >> 4;   // 61
    LDc(0); STSc(0); __syncthreads();

    for (int c = 0; c < nch; c++){
        int buf = c & 1;
        bool more = (c + 1) < nch;
        if (more) LDc(c + 1);
        int rem = TTn - c*16; if (rem > 16) rem = 16;

        for (int tt = 0; tt < rem; tt++){
            float dtv = sDT[buf][tt][q];
            float xv  = sXc[buf][tt][q];
            float4 Bv = *(float4*)&sBC[buf][tt][lane*4];
            float4 Cv = *(float4*)&sBC[buf][tt][16 + lane*4];
            float Bj[4] = {Bv.x, Bv.y, Bv.z, Bv.w};
            float Cj[4] = {Cv.x, Cv.y, Cv.z, Cv.w};
            float dtx = dtv * xv;
            float y = 0.f;
#pragma unroll
            for (int j = 0; j < 4; j++){
                float a = fexp2(dtv * cA[j]);
                h[j] = fmaf(h[j], a, dtx * Bj[j]);
                y    = fmaf(h[j], Cj[j], y);
            }
            y += __shfl_xor_sync(0xffffffffu, y, 1);
            y += __shfl_xor_sync(0xffffffffu, y, 2);
            if (lane == 0) sY[tt][q] = fmaf(Dv, xv, y);
        }
        __syncthreads();
        if (tld < rem){
            float4 yv = *(float4*)&sY[tld][fld*4];
            float4 zv = *(float4*)&sZc[buf][tld][fld*4];
            yv.x *= silu_f(zv.x); yv.y *= silu_f(zv.y);
            yv.z *= silu_f(zv.z); yv.w *= silu_f(zv.w);
            *(float4*)(Y + (size_t)(mb + c*16 + tld)*DIn + d0 + fld*4) = yv;
        }
        if (more){
            STSc(buf ^ 1);
            __syncthreads();
        }
    }
}

// ---------------- fused combine + LayerNorm ----------------
__global__ void combine_ln_kernel(const float* __restrict__ gam, const float* __restrict__ bet)
{
    int m = blockIdx.x, tid = threadIdx.x;
    float v[3];
#pragma unroll
    for (int i=0;i<3;i++){
        int c = tid + i*128;
        size_t o = (size_t)m*CCn + c;
        float fm = g_FMBM[o];
        float bm = g_FMBM[(size_t)MMn*CCn + o];
        float rl = g_RELU[o];
        v[i] = bm*(rl + fm);
        g_X[o] = v[i];
    }
    float s = v[0]+v[1]+v[2];
    float q = v[0]*v[0] + v[1]*v[1] + v[2]*v[2];
#pragma unroll
    for (int off=16; off; off>>=1){
        s += __shfl_xor_sync(0xffffffffu, s, off);
        q += __shfl_xor_sync(0xffffffffu, q, off);
    }
    __shared__ float ss[4], sq[4];
    if ((tid & 31) == 0){ ss[tid>>5] = s; sq[tid>>5] = q; }
    __syncthreads();
    s = ss[0]+ss[1]+ss[2]+ss[3];
    q = sq[0]+sq[1]+sq[2]+sq[3];
    float mean = s * (1.0f/384.0f);
    float var  = q * (1.0f/384.0f) - mean*mean;
    float rstd = rsqrtf(var + 1e-5f);
#pragma unroll
    for (int i=0;i<3;i++){
        int c = tid + i*128;
        g_XLN[(size_t)m*CCn + c] = (v[i]-mean)*rstd*gam[c] + bet[c];
    }
}

// ---------------- final LN + scatter ----------------
__global__ void final_kernel(const float* __restrict__ gam, const float* __restrict__ bet,
                             float* __restrict__ out)
{
    int m = blockIdx.x, tid = threadIdx.x;
    int b = m / TTn, t = m - b*TTn;
    const float* row = g_X + (size_t)m*CCn;
    float v0 = row[tid], v1 = row[tid+128], v2 = row[tid+256];
    float s = v0+v1+v2;
    float q = v0*v0 + v1*v1 + v2*v2;
#pragma unroll
    for (int off=16; off; off>>=1){
        s += __shfl_xor_sync(0xffffffffu, s, off);
        q += __shfl_xor_sync(0xffffffffu, q, off);
    }
    __shared__ float ss[4], sq[4];
    if ((tid & 31) == 0){ ss[tid>>5] = s; sq[tid>>5] = q; }
    __syncthreads();
    s = ss[0]+ss[1]+ss[2]+ss[3];
    q = sq[0]+sq[1]+sq[2]+sq[3];
    float mean = s * (1.0f/384.0f);
    float var  = q * (1.0f/384.0f) - mean*mean;
    float rstd = rsqrtf(var + 1e-5f);
    float vs[3] = {v0, v1, v2};
#pragma unroll
    for (int i=0;i<3;i++){
        int c = tid + i*128;
        float val = (vs[i]-mean)*rstd*gam[c] + bet[c];
        size_t dst;
        if (t < 960){
            int qq = t >> 6, p = t & 63;
            int sec = qq / 5, sidx = qq - sec*5;
            dst = (size_t)sec*IMG_BLK + (((size_t)((b*5+sidx)*384 + c)) << 6) + p;
        } else {
            dst = (size_t)3*IMG_BLK + (size_t)(b*2 + (t-960))*384 + c;
        }
        out[dst] = val;
    }
}

// ---------------- launch ----------------
extern "C" void kernel_launch(void* const* d_in, const int* in_sizes, int n_in,
                              void* d_out, int out_size)
{
    const float* img      = (const float*)d_in[0];
    const float* lid      = (const float*)d_in[1];
    const float* rad      = (const float*)d_in[2];
    const float* gps      = (const float*)d_in[3];
    const float* pos      = (const float*)d_in[4];
    const float* ln1_g    = (const float*)d_in[5];
    const float* ln1_b    = (const float*)d_in[6];
    const float* fc1_w    = (const float*)d_in[7];
    const float* fc1_b    = (const float*)d_in[8];
    const float* fc2_w    = (const float*)d_in[9];
    const float* fc2_b    = (const float*)d_in[10];
    const float* in_proj_w= (const float*)d_in[11];
    const float* conv_w   = (const float*)d_in[12];
    const float* conv_b   = (const float*)d_in[13];
    const float* x_proj_w = (const float*)d_in[14];
    const float* dt_proj_w= (const float*)d_in[15];
    const float* dt_proj_b= (const float*)d_in[16];
    const float* A_log    = (const float*)d_in[17];
    const float* D_param  = (const float*)d_in[18];
    const float* out_proj_w=(const float*)d_in[19];
    const float* ln_f_g   = (const float*)d_in[20];
    const float* ln_f_b   = (const float*)d_in[21];

    float *pX, *pXLN, *pXFC1, *pXFLIP, *pRELU, *pXZ2, *pXCONV2, *pXDBL2, *pDT2, *pY2, *pFMBM;
    cudaGetSymbolAddress((void**)&pX,     g_X);
    cudaGetSymbolAddress((void**)&pXLN,   g_XLN);
    cudaGetSymbolAddress((void**)&pXFC1,  g_XFC1);
    cudaGetSymbolAddress((void**)&pXFLIP, g_XFLIP);
    cudaGetSymbolAddress((void**)&pRELU,  g_RELU);
    cudaGetSymbolAddress((void**)&pXZ2,   g_XZ2);
    cudaGetSymbolAddress((void**)&pXCONV2,g_XCONV2);
    cudaGetSymbolAddress((void**)&pXDBL2, g_XDBL2);
    cudaGetSymbolAddress((void**)&pDT2,   g_DT2);
    cudaGetSymbolAddress((void**)&pY2,    g_Y2);
    cudaGetSymbolAddress((void**)&pFMBM,  g_FMBM);

    cudaFuncSetAttribute(mma_gemm3<0>, cudaFuncAttributeMaxDynamicSharedMemorySize, SMEM_G2);
    cudaFuncSetAttribute(mma_gemm3<2>, cudaFuncAttributeMaxDynamicSharedMemorySize, SMEM_G2);
    cudaFuncSetAttribute(mma_gemm3<3>, cudaFuncAttributeMaxDynamicSharedMemorySize, SMEM_G2);
    cudaFuncSetAttribute(mma_gemm3<4>, cudaFuncAttributeMaxDynamicSharedMemorySize, SMEM_G2);

    assemble_kernel<<<dim3(TTn, BZn), 384>>>(img, lid, rad, gps, pos);
    ln_kernel<<<MMn,128>>>(pX, ln1_g, ln1_b, pXLN);

    const int gm = (MMn + 127) / 128;              // 121
    const int CW = (MMn*(DIn/4) + 255)/256;

    for (int l = 0; l < 4; l++){
        // fc1 (+bias) with fused time-flip: XLN -> XFC1 and XFLIP
        mma_gemm3<4><<<dim3(gm,3,1),256,SMEM_G2>>>(
            pXLN, pXLN, CCn, fc1_w + (size_t)l*CCn*CCn, CCn, 0,
            fc1_b + (size_t)l*CCn, 0, pXFC1, 0, pXFLIP, MMn, CCn, CCn, CCn);
        // in_proj, both dirs
        mma_gemm3<0><<<dim3(gm,12,2),256,SMEM_G2>>>(
            pXFC1, pXFLIP, CCn, in_proj_w + (size_t)l*2*2*DIn*CCn, CCn, (size_t)2*DIn*CCn,
            nullptr, 0, pXZ2, (size_t)MMn*2*DIn, nullptr, MMn, 2*DIn, CCn, CCn);
        conv_silu4_kernel<<<dim3(CW,2),256>>>(conv_w + (size_t)l*2*DIn*4,
                                              conv_b + (size_t)l*2*DIn);
        // x_proj, both dirs
        mma_gemm3<0><<<dim3(gm,1,2),256,SMEM_G2>>>(
            pXCONV2, pXCONV2 + (size_t)MMn*DIn, DIn,
            x_proj_w + (size_t)l*2*XPn*DIn, DIn, (size_t)XPn*DIn,
            nullptr, 0, pXDBL2, (size_t)MMn*XPn, nullptr, MMn, XPn, DIn, DIn);
        // dt_proj (+softplus), both dirs: K=24 padded to 32
        mma_gemm3<3><<<dim3(gm,6,2),256,SMEM_G2>>>(
            pXDBL2, pXDBL2 + (size_t)MMn*XPn, XPn,
            dt_proj_w + (size_t)l*2*DIn*DTRn, DTRn, (size_t)DIn*DTRn,
            dt_proj_b + (size_t)l*2*DIn, DIn, pDT2, (size_t)MMn*DIn, nullptr,
            MMn, DIn, 32, DTRn);
        scan2_kernel<<<dim3(24,BZn,2),128>>>(A_log + (size_t)l*2*DIn*DSTn,
                                             D_param + (size_t)l*2*DIn);
        // out_proj, both dirs -> FMBM[0]=FM, FMBM[1]=BM
        mma_gemm3<0><<<dim3(gm,3,2),256,SMEM_G2>>>(
            pY2, pY2 + (size_t)MMn*DIn, DIn,
            out_proj_w + (size_t)l*2*CCn*DIn, DIn, (size_t)CCn*DIn,
            nullptr, 0, pFMBM, (size_t)MMn*CCn, nullptr, MMn, CCn, DIn, DIn);
        // fc2 + leaky: XFLIP -> RELU
        mma_gemm3<2><<<dim3(gm,3,1),256,SMEM_G2>>>(
            pXFLIP, pXFLIP, CCn, fc2_w + (size_t)l*CCn*CCn, CCn, 0,
            fc2_b + (size_t)l*CCn, 0, pRELU, 0, nullptr, MMn, CCn, CCn, CCn);
        // combine + LN (next layer's params; harmless extra XLN on last layer)
        int ln_next = (l < 3) ? (l+1) : 3;
        combine_ln_kernel<<<MMn,128>>>(ln1_g + (size_t)ln_next*CCn,
                                       ln1_b + (size_t)ln_next*CCn);
    }

    final_kernel<<<MMn,128>>>(ln_f_g, ln_f_b, (float*)d_out);
}

// round 17
// speedup vs baseline: 2.7240x; 1.0456x over previous
#include <cuda_runtime.h>
#include <cuda_bf16.h>
#include <cstdint>

// ---------------- problem constants ----------------
#define BZn   16
#define TTn   962
#define CCn   384
#define DIn   768
#define DSTn  16
#define DTRn  24
#define XPn   56          // DTR + 2*DSTATE
#define MMn   (BZn*TTn)   // 15392
#define IMG_BLK 1966080   // 80*384*64

// ---------------- scratch (device globals; no allocation allowed) ----------------
__device__ __align__(16) float g_X    [MMn*CCn];
__device__ __align__(16) float g_XLN  [MMn*CCn];
__device__ __align__(16) float g_XFC1 [MMn*CCn];
__device__ __align__(16) float g_XFLIP[MMn*CCn];
__device__ __align__(16) float g_RELU [MMn*CCn];
// per-direction branch buffers (dir-major)
__device__ __align__(16) float g_XZ2   [2*(size_t)MMn*2*DIn];
__device__ __align__(16) float g_XCONV2[2*(size_t)MMn*DIn];
__device__ __align__(16) float g_XDBL2 [2*(size_t)MMn*XPn];
__device__ __align__(16) float g_DT2   [2*(size_t)MMn*DIn];
__device__ __align__(16) float g_Y2    [2*(size_t)MMn*DIn];
__device__ __align__(16) float g_FMBM  [2*(size_t)MMn*CCn];   // [0]=FM fwd, [1]=BM bwd

// ---------------- MUFU-free math helpers ----------------
__device__ __forceinline__ float fexp2(float y){
    y = fminf(fmaxf(y, -126.f), 126.f);
    float n = rintf(y);
    float f = y - n;
    float g = f * 0.69314718055994531f;
    float p = 1.98412698e-4f;
    p = fmaf(p, g, 1.38888889e-3f);
    p = fmaf(p, g, 8.33333333e-3f);
    p = fmaf(p, g, 4.16666667e-2f);
    p = fmaf(p, g, 1.66666667e-1f);
    p = fmaf(p, g, 0.5f);
    p = fmaf(p, g, 1.0f);
    p = fmaf(p, g, 1.0f);
    return p * __int_as_float(((int)n + 127) << 23);
}
__device__ __forceinline__ float fexp(float x){ return fexp2(x * 1.4426950408889634f); }
__device__ __forceinline__ float frcp_fast(float w){
    float r = __int_as_float(0x7EF311C3 - __float_as_int(w));
    r = r * fmaf(-w, r, 2.0f);
    r = r * fmaf(-w, r, 2.0f);
    r = r * fmaf(-w, r, 2.0f);
    return r;
}
__device__ __forceinline__ float silu_f(float x){ return x * frcp_fast(1.0f + fexp(-x)); }
__device__ __forceinline__ float softplus_f(float x){
    float ax = fabsf(x);
    float e  = fexp(-ax);
    float t  = e * frcp_fast(2.0f + e);
    float t2 = t * t;
    float p  = 2.0f/9.0f;
    p = fmaf(p, t2, 2.0f/7.0f);
    p = fmaf(p, t2, 2.0f/5.0f);
    p = fmaf(p, t2, 2.0f/3.0f);
    p = fmaf(p, t2, 2.0f);
    return fmaxf(x, 0.0f) + p * t;
}

// ---------------- mma / ldmatrix helpers (non-'a' features, sm_80+) ----------------
__device__ __forceinline__ uint32_t sptr(const void* p){
    return (uint32_t)__cvta_generic_to_shared(p);
}
__device__ __forceinline__ void ldm_x4(uint32_t r[4], uint32_t addr){
    asm volatile("ldmatrix.sync.aligned.m8n8.x4.shared.b16 {%0,%1,%2,%3}, [%4];"
        : "=r"(r[0]), "=r"(r[1]), "=r"(r[2]), "=r"(r[3]) : "r"(addr));
}
__device__ __forceinline__ void mma_bf16(float* d, const uint32_t* a, const uint32_t* b){
    asm volatile("mma.sync.aligned.m16n8k16.row.col.f32.bf16.bf16.f32 "
        "{%0,%1,%2,%3}, {%4,%5,%6,%7}, {%8,%9}, {%0,%1,%2,%3};"
        : "+f"(d[0]), "+f"(d[1]), "+f"(d[2]), "+f"(d[3])
        : "r"(a[0]), "r"(a[1]), "r"(a[2]), "r"(a[3]), "r"(b[0]), "r"(b[1]));
}
__device__ __forceinline__ uint32_t pk2(float x, float y){
    __nv_bfloat162 t(__float2bfloat16(x), __float2bfloat16(y));
    return *reinterpret_cast<uint32_t*>(&t);
}
// split 4 fp32 -> 4 bf16 hi + 4 bf16 lo
__device__ __forceinline__ void split4(const float4& a, uint2& hi, uint2& lo){
    float h0 = __bfloat162float(__float2bfloat16(a.x));
    float h1 = __bfloat162float(__float2bfloat16(a.y));
    float h2 = __bfloat162float(__float2bfloat16(a.z));
    float h3 = __bfloat162float(__float2bfloat16(a.w));
    hi.x = pk2(a.x, a.y);         hi.y = pk2(a.z, a.w);
    lo.x = pk2(a.x - h0, a.y - h1); lo.y = pk2(a.z - h2, a.w - h3);
}

// ---------------- pipelined HMMA GEMM, bf16x3, dual-direction via blockIdx.z ------
// 128x128 block tile, 4 warps (warp tile 64x64), 128 threads, 2 CTAs/SM.
// Co[m,n] = sum_k A[m,k]*W[n,k].
// EPI: 0=none 1=bias 2=bias+leaky 3=bias+softplus 4=bias + dual store (Co + flipped Co2)
#define PLANEn (128*40)
template<int EPI>
__global__ void __launch_bounds__(128, 2)
mma_gemm4(const float* __restrict__ A0, const float* __restrict__ A1, int lda,
          const float* __restrict__ W, int ldw, size_t wsz,
          const float* __restrict__ bias, size_t bsz,
          float* __restrict__ Co, size_t csz, float* __restrict__ Co2,
          int M, int N, int Kloop, int Klim)
{
    extern __shared__ __align__(16) __nv_bfloat16 sm[];   // 2 bufs x 4 planes x 128x40

    const int dir = blockIdx.z;
    const float* A = dir ? A1 : A0;
    W  += (size_t)dir * wsz;
    Co += (size_t)dir * csz;
    if (EPI >= 1) bias += (size_t)dir * bsz;

    const int tid = threadIdx.x;
    const int lid = tid & 31, wid = tid >> 5;      // 4 warps
    const int warp_m = wid & 1, warp_n = wid >> 1; // 2x2 -> 64x64 warp tile
    const int m0 = blockIdx.x * 128, n0 = blockIdx.y * 128;
    const int rg  = tid >> 3;      // 0..15 (row group)
    const int sub = tid & 7;       // 0..7  (float4 column within 32-float row)

    float acc[4][8][4];
#pragma unroll
    for (int i=0;i<4;i++)
#pragma unroll
        for (int j=0;j<8;j++)
#pragma unroll
            for (int q=0;q<4;q++) acc[i][j][q] = 0.f;

    float4 rr[8];                  // staged prefetch (A then B reuse)

    auto LD_A = [&](int kb){
        int c = kb + sub*4;
        bool kok = (c + 3) < Klim;
#pragma unroll
        for (int rep=0; rep<8; rep++){
            int row = rg + rep*16;
            rr[rep] = (kok && (m0+row) < M) ?
                *(const float4*)(A + (size_t)(m0+row)*lda + c) : make_float4(0,0,0,0);
        }
    };
    auto LD_B = [&](int kb){
        int c = kb + sub*4;
        bool kok = (c + 3) < Klim;
#pragma unroll
        for (int rep=0; rep<8; rep++){
            int row = rg + rep*16;
            rr[rep] = (kok && (n0+row) < N) ?
                *(const float4*)(W + (size_t)(n0+row)*ldw + c) : make_float4(0,0,0,0);
        }
    };
    auto STS_A = [&](int buf){
        __nv_bfloat16* base = sm + buf*4*PLANEn;
#pragma unroll
        for (int rep=0; rep<8; rep++){
            int row = rg + rep*16;
            int bo = row*40 + sub*4;
            uint2 hi, lo;
            split4(rr[rep], hi, lo);
            *(uint2*)(base + bo) = hi;
            *(uint2*)(base + PLANEn + bo) = lo;
        }
    };
    auto STS_B = [&](int buf){
        __nv_bfloat16* base = sm + buf*4*PLANEn + 2*PLANEn;
#pragma unroll
        for (int rep=0; rep<8; rep++){
            int row = rg + rep*16;
            int bo = row*40 + sub*4;
            uint2 hi, lo;
            split4(rr[rep], hi, lo);
            *(uint2*)(base + bo) = hi;
            *(uint2*)(base + PLANEn + bo) = lo;
        }
    };
    auto COMP = [&](int buf, int kk){
        __nv_bfloat16* Ah = sm + buf*4*PLANEn;
        __nv_bfloat16* Al = Ah + PLANEn;
        __nv_bfloat16* Bh = Ah + 2*PLANEn;
        __nv_bfloat16* Bl = Ah + 3*PLANEn;
        uint32_t ah[4][4], al[4][4];
#pragma unroll
        for (int i=0;i<4;i++){
            int arow = warp_m*64 + i*16 + (lid & 15);
            int acol = kk*16 + (lid >> 4)*8;
            ldm_x4(ah[i], sptr(Ah + arow*40 + acol));
            ldm_x4(al[i], sptr(Al + arow*40 + acol));
        }
#pragma unroll
        for (int jp=0; jp<4; jp++){
            uint32_t bh[4], bl[4];
            int brow = warp_n*64 + jp*16 + ((lid >> 4) << 3) + (lid & 7);
            int bcol = kk*16 + ((lid >> 3) & 1)*8;
            ldm_x4(bh, sptr(Bh + brow*40 + bcol));
            ldm_x4(bl, sptr(Bl + brow*40 + bcol));
#pragma unroll
            for (int i=0;i<4;i++){
                mma_bf16(acc[i][jp*2],   ah[i], &bh[0]);
                mma_bf16(acc[i][jp*2],   al[i], &bh[0]);
                mma_bf16(acc[i][jp*2],   ah[i], &bl[0]);
                mma_bf16(acc[i][jp*2+1], ah[i], &bh[2]);
                mma_bf16(acc[i][jp*2+1], al[i], &bh[2]);
                mma_bf16(acc[i][jp*2+1], ah[i], &bl[2]);
            }
        }
    };

    // prologue
    LD_A(0); STS_A(0);
    LD_B(0); STS_B(0);
    __syncthreads();

    const int nkc = Kloop >> 5;
    for (int kc = 0; kc < nkc; kc++){
        int cur = kc & 1, nb = cur ^ 1;
        bool more = (kc + 1) < nkc;
        int kbn = (kc + 1) << 5;
        if (more) LD_A(kbn);
        COMP(cur, 0);
        if (more){ STS_A(nb); LD_B(kbn); }
        COMP(cur, 1);
        if (more){ STS_B(nb); __syncthreads(); }
    }

    // epilogue
#pragma unroll
    for (int i=0;i<4;i++){
#pragma unroll
        for (int j=0;j<8;j++){
            int r = m0 + warp_m*64 + i*16 + (lid >> 2);
            int c = n0 + warp_n*64 + j*8 + (lid & 3)*2;
            if (c < N){
                float b0 = 0.f, b1 = 0.f;
                if (EPI >= 1){ b0 = bias[c]; b1 = bias[c+1]; }
                float v0 = acc[i][j][0] + b0, v1 = acc[i][j][1] + b1;
                float v2 = acc[i][j][2] + b0, v3 = acc[i][j][3] + b1;
                if (EPI == 2){
                    v0 = (v0 >= 0.f) ? v0 : 0.2f*v0;
                    v1 = (v1 >= 0.f) ? v1 : 0.2f*v1;
                    v2 = (v2 >= 0.f) ? v2 : 0.2f*v2;
                    v3 = (v3 >= 0.f) ? v3 : 0.2f*v3;
                }
                if (EPI == 3){
                    v0 = softplus_f(v0); v1 = softplus_f(v1);
                    v2 = softplus_f(v2); v3 = softplus_f(v3);
                }
                if (r < M){
                    *(float2*)(Co + (size_t)r*N + c) = make_float2(v0, v1);
                    if (EPI == 4){
                        int bb = r / TTn, tt = r - bb*TTn;
                        int r2 = bb*TTn + (TTn-1 - tt);
                        *(float2*)(Co2 + (size_t)r2*N + c) = make_float2(v0, v1);
                    }
                }
                if (r + 8 < M){
                    *(float2*)(Co + (size_t)(r+8)*N + c) = make_float2(v2, v3);
                    if (EPI == 4){
                        int bb = (r+8) / TTn, tt = (r+8) - bb*TTn;
                        int r2 = bb*TTn + (TTn-1 - tt);
                        *(float2*)(Co2 + (size_t)r2*N + c) = make_float2(v2, v3);
                    }
                }
            }
        }
    }
}
#define SMEM_G2 (2*4*PLANEn*2)   // 81920 bytes

// ---------------- token assembly ----------------
__global__ void assemble_kernel(const float* __restrict__ img,
                                const float* __restrict__ lid,
                                const float* __restrict__ rad,
                                const float* __restrict__ gps,
                                const float* __restrict__ pos)
{
    int c = threadIdx.x;
    int t = blockIdx.x;
    int b = blockIdx.y;
    float v;
    if (t < 960){
        int q = t >> 6, p = t & 63;
        int grp = q / 5, s = q - grp*5;
        int band = c >> 7;
        int code = grp + band; if (code >= 3) code -= 3;
        const float* sel = (code == 0) ? img : (code == 1) ? lid : rad;
        v = sel[((size_t)((b*5 + s)*384 + c) << 6) + p];
    } else {
        v = gps[((size_t)(b*2 + (t-960)))*384 + c];
    }
    g_X[((size_t)(b*TTn + t))*CCn + c] = v + pos[t*CCn + c];
}

// ---------------- LayerNorm (standalone; layer-0 input) ----------------
__global__ void ln_kernel(const float* __restrict__ x, const float* __restrict__ gam,
                          const float* __restrict__ bet, float* __restrict__ out)
{
    int m = blockIdx.x, tid = threadIdx.x;
    const float* row = x + (size_t)m*CCn;
    float v0 = row[tid], v1 = row[tid+128], v2 = row[tid+256];
    float s = v0+v1+v2;
    float q = v0*v0 + v1*v1 + v2*v2;
#pragma unroll
    for (int off=16; off; off>>=1){
        s += __shfl_xor_sync(0xffffffffu, s, off);
        q += __shfl_xor_sync(0xffffffffu, q, off);
    }
    __shared__ float ss[4], sq[4];
    if ((tid & 31) == 0){ ss[tid>>5] = s; sq[tid>>5] = q; }
    __syncthreads();
    s = ss[0]+ss[1]+ss[2]+ss[3];
    q = sq[0]+sq[1]+sq[2]+sq[3];
    float mean = s * (1.0f/384.0f);
    float var  = q * (1.0f/384.0f) - mean*mean;
    float rstd = rsqrtf(var + 1e-5f);
    float* orow = out + (size_t)m*CCn;
    orow[tid]     = (v0-mean)*rstd*gam[tid]     + bet[tid];
    orow[tid+128] = (v1-mean)*rstd*gam[tid+128] + bet[tid+128];
    orow[tid+256] = (v2-mean)*rstd*gam[tid+256] + bet[tid+256];
}

// ---------------- depthwise causal conv + SiLU (float4 over d, dual-dir) ---------
__global__ void conv_silu4_kernel(const float* __restrict__ cwb, const float* __restrict__ cbb){
    int dir = blockIdx.y;
    const float* cw = cwb + (size_t)dir*DIn*4;
    const float* cb = cbb + (size_t)dir*DIn;
    const float* XZ = g_XZ2 + (size_t)dir*MMn*2*DIn;
    float* XC = g_XCONV2 + (size_t)dir*MMn*DIn;

    int idx = blockIdx.x*blockDim.x + threadIdx.x;
    if (idx >= MMn*(DIn/4)) return;
    int d4 = (idx % (DIn/4))*4;
    int m = idx / (DIn/4);
    int b = m / TTn;
    int t = m - b*TTn;
    const float* base = XZ + (size_t)(b*TTn)*(2*DIn) + d4;
    float4 w0 = *(const float4*)(cw + (size_t)(d4+0)*4);
    float4 w1 = *(const float4*)(cw + (size_t)(d4+1)*4);
    float4 w2 = *(const float4*)(cw + (size_t)(d4+2)*4);
    float4 w3 = *(const float4*)(cw + (size_t)(d4+3)*4);
    float4 acc = *(const float4*)(cb + d4);
    if (t >= 3){
        float4 v = *(const float4*)(base + (size_t)(t-3)*(2*DIn));
        acc.x = fmaf(w0.x, v.x, acc.x); acc.y = fmaf(w1.x, v.y, acc.y);
        acc.z = fmaf(w2.x, v.z, acc.z); acc.w = fmaf(w3.x, v.w, acc.w);
    }
    if (t >= 2){
        float4 v = *(const float4*)(base + (size_t)(t-2)*(2*DIn));
        acc.x = fmaf(w0.y, v.x, acc.x); acc.y = fmaf(w1.y, v.y, acc.y);
        acc.z = fmaf(w2.y, v.z, acc.z); acc.w = fmaf(w3.y, v.w, acc.w);
    }
    if (t >= 1){
        float4 v = *(const float4*)(base + (size_t)(t-1)*(2*DIn));
        acc.x = fmaf(w0.z, v.x, acc.x); acc.y = fmaf(w1.z, v.y, acc.y);
        acc.z = fmaf(w2.z, v.z, acc.z); acc.w = fmaf(w3.z, v.w, acc.w);
    }
    {
        float4 v = *(const float4*)(base + (size_t)t*(2*DIn));
        acc.x = fmaf(w0.w, v.x, acc.x); acc.y = fmaf(w1.w, v.y, acc.y);
        acc.z = fmaf(w2.w, v.z, acc.z); acc.w = fmaf(w3.w, v.w, acc.w);
    }
    float4 o;
    o.x = silu_f(acc.x); o.y = silu_f(acc.y); o.z = silu_f(acc.z); o.w = silu_f(acc.w);
    *(float4*)(XC + (size_t)m*DIn + d4) = o;
}

// ---------------- selective scan: smem-staged, double-buffered, dual-dir ---------
__global__ void __launch_bounds__(128)
scan2_kernel(const float* __restrict__ a_logb, const float* __restrict__ Dpb){
    __shared__ float sDT[2][16][32], sXc[2][16][32], sZc[2][16][32], sBC[2][16][32];
    __shared__ float sY[16][32];

    const int dir = blockIdx.z;
    const float* a_log = a_logb + (size_t)dir*DIn*DSTn;
    const float* Dp    = Dpb   + (size_t)dir*DIn;
    const float* DT  = g_DT2   + (size_t)dir*MMn*DIn;
    const float* XC  = g_XCONV2+ (size_t)dir*MMn*DIn;
    const float* XZ  = g_XZ2   + (size_t)dir*MMn*2*DIn;
    const float* XD  = g_XDBL2 + (size_t)dir*MMn*XPn;
    float*       Y   = g_Y2    + (size_t)dir*MMn*DIn;

    const int tid = threadIdx.x;
    const int q = tid >> 2, lane = tid & 3;
    const int b = blockIdx.y;
    const int d0 = blockIdx.x * 32;
    const int d = d0 + q;
    const int mb = b * TTn;

    float4 av = *(const float4*)(a_log + (size_t)d*16 + lane*4);
    float cA[4] = { -fexp(av.x)*1.4426950408889634f, -fexp(av.y)*1.4426950408889634f,
                    -fexp(av.z)*1.4426950408889634f, -fexp(av.w)*1.4426950408889634f };
    float h[4] = {0.f,0.f,0.f,0.f};
    float Dv = Dp[d];

    const int tld = tid >> 3;
    const int fld = tid & 7;
    float4 rDT, rX, rZ, rBC;

    auto LDc = [&](int c){
        int t = c*16 + tld;
        if (t < TTn){
            size_t m = (size_t)(mb + t);
            rDT = *(const float4*)(DT + m*DIn + d0 + fld*4);
            rX  = *(const float4*)(XC + m*DIn + d0 + fld*4);
            rZ  = *(const float4*)(XZ + m*(2*DIn) + DIn + d0 + fld*4);
            rBC = *(const float4*)(XD + m*XPn + 24 + fld*4);
        } else {
            rDT = rX = rZ = rBC = make_float4(0,0,0,0);
        }
    };
    auto STSc = [&](int buf){
        *(float4*)&sDT[buf][tld][fld*4] = rDT;
        *(float4*)&sXc[buf][tld][fld*4] = rX;
        *(float4*)&sZc[buf][tld][fld*4] = rZ;
        *(float4*)&sBC[buf][tld][fld*4] = rBC;
    };

    const int nch = (TTn + 15) >> 4;   // 61
    LDc(0); STSc(0); __syncthreads();

    for (int c = 0; c < nch; c++){
        int buf = c & 1;
        bool more = (c + 1) < nch;
        if (more) LDc(c + 1);
        int rem = TTn - c*16; if (rem > 16) rem = 16;

        for (int tt = 0; tt < rem; tt++){
            float dtv = sDT[buf][tt][q];
            float xv  = sXc[buf][tt][q];
            float4 Bv = *(float4*)&sBC[buf][tt][lane*4];
            float4 Cv = *(float4*)&sBC[buf][tt][16 + lane*4];
            float Bj[4] = {Bv.x, Bv.y, Bv.z, Bv.w};
            float Cj[4] = {Cv.x, Cv.y, Cv.z, Cv.w};
            float dtx = dtv * xv;
            float y = 0.f;
#pragma unroll
            for (int j = 0; j < 4; j++){
                float a = fexp2(dtv * cA[j]);
                h[j] = fmaf(h[j], a, dtx * Bj[j]);
                y    = fmaf(h[j], Cj[j], y);
            }
            y += __shfl_xor_sync(0xffffffffu, y, 1);
            y += __shfl_xor_sync(0xffffffffu, y, 2);
            if (lane == 0) sY[tt][q] = fmaf(Dv, xv, y);
        }
        __syncthreads();
        if (tld < rem){
            float4 yv = *(float4*)&sY[tld][fld*4];
            float4 zv = *(float4*)&sZc[buf][tld][fld*4];
            yv.x *= silu_f(zv.x); yv.y *= silu_f(zv.y);
            yv.z *= silu_f(zv.z); yv.w *= silu_f(zv.w);
            *(float4*)(Y + (size_t)(mb + c*16 + tld)*DIn + d0 + fld*4) = yv;
        }
        if (more){
            STSc(buf ^ 1);
            __syncthreads();
        }
    }
}

// ---------------- fused combine + LayerNorm ----------------
__global__ void combine_ln_kernel(const float* __restrict__ gam, const float* __restrict__ bet)
{
    int m = blockIdx.x, tid = threadIdx.x;
    float v[3];
#pragma unroll
    for (int i=0;i<3;i++){
        int c = tid + i*128;
        size_t o = (size_t)m*CCn + c;
        float fm = g_FMBM[o];
        float bm = g_FMBM[(size_t)MMn*CCn + o];
        float rl = g_RELU[o];
        v[i] = bm*(rl + fm);
        g_X[o] = v[i];
    }
    float s = v[0]+v[1]+v[2];
    float q = v[0]*v[0] + v[1]*v[1] + v[2]*v[2];
#pragma unroll
    for (int off=16; off; off>>=1){
        s += __shfl_xor_sync(0xffffffffu, s, off);
        q += __shfl_xor_sync(0xffffffffu, q, off);
    }
    __shared__ float ss[4], sq[4];
    if ((tid & 31) == 0){ ss[tid>>5] = s; sq[tid>>5] = q; }
    __syncthreads();
    s = ss[0]+ss[1]+ss[2]+ss[3];
    q = sq[0]+sq[1]+sq[2]+sq[3];
    float mean = s * (1.0f/384.0f);
    float var  = q * (1.0f/384.0f) - mean*mean;
    float rstd = rsqrtf(var + 1e-5f);
#pragma unroll
    for (int i=0;i<3;i++){
        int c = tid + i*128;
        g_XLN[(size_t)m*CCn + c] = (v[i]-mean)*rstd*gam[c] + bet[c];
    }
}

// ---------------- final LN + scatter ----------------
__global__ void final_kernel(const float* __restrict__ gam, const float* __restrict__ bet,
                             float* __restrict__ out)
{
    int m = blockIdx.x, tid = threadIdx.x;
    int b = m / TTn, t = m - b*TTn;
    const float* row = g_X + (size_t)m*CCn;
    float v0 = row[tid], v1 = row[tid+128], v2 = row[tid+256];
    float s = v0+v1+v2;
    float q = v0*v0 + v1*v1 + v2*v2;
#pragma unroll
    for (int off=16; off; off>>=1){
        s += __shfl_xor_sync(0xffffffffu, s, off);
        q += __shfl_xor_sync(0xffffffffu, q, off);
    }
    __shared__ float ss[4], sq[4];
    if ((tid & 31) == 0){ ss[tid>>5] = s; sq[tid>>5] = q; }
    __syncthreads();
    s = ss[0]+ss[1]+ss[2]+ss[3];
    q = sq[0]+sq[1]+sq[2]+sq[3];
    float mean = s * (1.0f/384.0f);
    float var  = q * (1.0f/384.0f) - mean*mean;
    float rstd = rsqrtf(var + 1e-5f);
    float vs[3] = {v0, v1, v2};
#pragma unroll
    for (int i=0;i<3;i++){
        int c = tid + i*128;
        float val = (vs[i]-mean)*rstd*gam[c] + bet[c];
        size_t dst;
        if (t < 960){
            int qq = t >> 6, p = t & 63;
            int sec = qq / 5, sidx = qq - sec*5;
            dst = (size_t)sec*IMG_BLK + (((size_t)((b*5+sidx)*384 + c)) << 6) + p;
        } else {
            dst = (size_t)3*IMG_BLK + (size_t)(b*2 + (t-960))*384 + c;
        }
        out[dst] = val;
    }
}

// ---------------- launch ----------------
extern "C" void kernel_launch(void* const* d_in, const int* in_sizes, int n_in,
                              void* d_out, int out_size)
{
    const float* img      = (const float*)d_in[0];
    const float* lid      = (const float*)d_in[1];
    const float* rad      = (const float*)d_in[2];
    const float* gps      = (const float*)d_in[3];
    const float* pos      = (const float*)d_in[4];
    const float* ln1_g    = (const float*)d_in[5];
    const float* ln1_b    = (const float*)d_in[6];
    const float* fc1_w    = (const float*)d_in[7];
    const float* fc1_b    = (const float*)d_in[8];
    const float* fc2_w    = (const float*)d_in[9];
    const float* fc2_b    = (const float*)d_in[10];
    const float* in_proj_w= (const float*)d_in[11];
    const float* conv_w   = (const float*)d_in[12];
    const float* conv_b   = (const float*)d_in[13];
    const float* x_proj_w = (const float*)d_in[14];
    const float* dt_proj_w= (const float*)d_in[15];
    const float* dt_proj_b= (const float*)d_in[16];
    const float* A_log    = (const float*)d_in[17];
    const float* D_param  = (const float*)d_in[18];
    const float* out_proj_w=(const float*)d_in[19];
    const float* ln_f_g   = (const float*)d_in[20];
    const float* ln_f_b   = (const float*)d_in[21];

    float *pX, *pXLN, *pXFC1, *pXFLIP, *pRELU, *pXZ2, *pXCONV2, *pXDBL2, *pDT2, *pY2, *pFMBM;
    cudaGetSymbolAddress((void**)&pX,     g_X);
    cudaGetSymbolAddress((void**)&pXLN,   g_XLN);
    cudaGetSymbolAddress((void**)&pXFC1,  g_XFC1);
    cudaGetSymbolAddress((void**)&pXFLIP, g_XFLIP);
    cudaGetSymbolAddress((void**)&pRELU,  g_RELU);
    cudaGetSymbolAddress((void**)&pXZ2,   g_XZ2);
    cudaGetSymbolAddress((void**)&pXCONV2,g_XCONV2);
    cudaGetSymbolAddress((void**)&pXDBL2, g_XDBL2);
    cudaGetSymbolAddress((void**)&pDT2,   g_DT2);
    cudaGetSymbolAddress((void**)&pY2,    g_Y2);
    cudaGetSymbolAddress((void**)&pFMBM,  g_FMBM);

    cudaFuncSetAttribute(mma_gemm4<0>, cudaFuncAttributeMaxDynamicSharedMemorySize, SMEM_G2);
    cudaFuncSetAttribute(mma_gemm4<2>, cudaFuncAttributeMaxDynamicSharedMemorySize, SMEM_G2);
    cudaFuncSetAttribute(mma_gemm4<3>, cudaFuncAttributeMaxDynamicSharedMemorySize, SMEM_G2);
    cudaFuncSetAttribute(mma_gemm4<4>, cudaFuncAttributeMaxDynamicSharedMemorySize, SMEM_G2);

    assemble_kernel<<<dim3(TTn, BZn), 384>>>(img, lid, rad, gps, pos);
    ln_kernel<<<MMn,128>>>(pX, ln1_g, ln1_b, pXLN);

    const int gm = (MMn + 127) / 128;              // 121
    const int CW = (MMn*(DIn/4) + 255)/256;

    for (int l = 0; l < 4; l++){
        // fc1 (+bias) with fused time-flip: XLN -> XFC1 and XFLIP
        mma_gemm4<4><<<dim3(gm,3,1),128,SMEM_G2>>>(
            pXLN, pXLN, CCn, fc1_w + (size_t)l*CCn*CCn, CCn, 0,
            fc1_b + (size_t)l*CCn, 0, pXFC1, 0, pXFLIP, MMn, CCn, CCn, CCn);
        // in_proj, both dirs
        mma_gemm4<0><<<dim3(gm,12,2),128,SMEM_G2>>>(
            pXFC1, pXFLIP, CCn, in_proj_w + (size_t)l*2*2*DIn*CCn, CCn, (size_t)2*DIn*CCn,
            nullptr, 0, pXZ2, (size_t)MMn*2*DIn, nullptr, MMn, 2*DIn, CCn, CCn);
        conv_silu4_kernel<<<dim3(CW,2),256>>>(conv_w + (size_t)l*2*DIn*4,
                                              conv_b + (size_t)l*2*DIn);
        // x_proj, both dirs
        mma_gemm4<0><<<dim3(gm,1,2),128,SMEM_G2>>>(
            pXCONV2, pXCONV2 + (size_t)MMn*DIn, DIn,
            x_proj_w + (size_t)l*2*XPn*DIn, DIn, (size_t)XPn*DIn,
            nullptr, 0, pXDBL2, (size_t)MMn*XPn, nullptr, MMn, XPn, DIn, DIn);
        // dt_proj (+softplus), both dirs: K=24 padded to 32
        mma_gemm4<3><<<dim3(gm,6,2),128,SMEM_G2>>>(
            pXDBL2, pXDBL2 + (size_t)MMn*XPn, XPn,
            dt_proj_w + (size_t)l*2*DIn*DTRn, DTRn, (size_t)DIn*DTRn,
            dt_proj_b + (size_t)l*2*DIn, DIn, pDT2, (size_t)MMn*DIn, nullptr,
            MMn, DIn, 32, DTRn);
        scan2_kernel<<<dim3(24,BZn,2),128>>>(A_log + (size_t)l*2*DIn*DSTn,
                                             D_param + (size_t)l*2*DIn);
        // out_proj, both dirs -> FMBM[0]=FM, FMBM[1]=BM
        mma_gemm4<0><<<dim3(gm,3,2),128,SMEM_G2>>>(
            pY2, pY2 + (size_t)MMn*DIn, DIn,
            out_proj_w + (size_t)l*2*CCn*DIn, DIn, (size_t)CCn*DIn,
            nullptr, 0, pFMBM, (size_t)MMn*CCn, nullptr, MMn, CCn, DIn, DIn);
        // fc2 + leaky: XFLIP -> RELU
        mma_gemm4<2><<<dim3(gm,3,1),128,SMEM_G2>>>(
            pXFLIP, pXFLIP, CCn, fc2_w + (size_t)l*CCn*CCn, CCn, 0,
            fc2_b + (size_t)l*CCn, 0, pRELU, 0, nullptr, MMn, CCn, CCn, CCn);
        // combine + LN (next layer's params; harmless extra XLN on last layer)
        int ln_next = (l < 3) ? (l+1) : 3;
        combine_ln_kernel<<<MMn,128>>>(ln1_g + (size_t)ln_next*CCn,
                                       ln1_b + (size_t)ln_next*CCn);
    }

    final_kernel<<<MMn,128>>>(ln_f_g, ln_f_b, (float*)d_out);
}